// round 2
// baseline (speedup 1.0000x reference)
#include <cuda_runtime.h>

#define NNODES 50000
#define NGRAPH 64
#define FIN    128
#define NCLS   10
#define MAXE   600000

// ---------------- scratch (static device arrays) -----------------------------
__device__ float g_xlr1[NNODES * 256];   // conv1: [xl(128) | xr(128)]
__device__ float g_h1  [NNODES * 128];   // conv1 output (post-ELU)
__device__ float g_xlr2[NNODES * 128];   // conv2: [xl(64) | xr(64)]
__device__ float g_pool[NGRAPH * 64];
__device__ float g_cnt [NGRAPH];
__device__ int   g_idx64;

__device__ int   g_deg     [NNODES];
__device__ int   g_rowstart[NNODES + 1];
__device__ int   g_cursor  [NNODES];
__device__ int   g_csr_src [MAXE];

// ---------------- helpers -----------------------------------------------------
__device__ __forceinline__ void red_add4(float* p, float4 v) {
    asm volatile("red.global.add.v4.f32 [%0], {%1,%2,%3,%4};"
                 :: "l"(p), "f"(v.x), "f"(v.y), "f"(v.z), "f"(v.w) : "memory");
}
__device__ __forceinline__ float lrelu(float v) { return v > 0.f ? v : 0.2f * v; }
__device__ __forceinline__ float elu(float v)   { return v > 0.f ? v : expm1f(v); }

// ---------------- dtype detection --------------------------------------------
__global__ void detect_idx_kernel(const void* ei) {
    if (threadIdx.x == 0) {
        const long long* p = (const long long*)ei;
        int ok = 1;
        for (int i = 0; i < 16; i++) {
            long long v = p[i];
            if (v < 0 || v >= NNODES) ok = 0;
        }
        g_idx64 = ok;
    }
}

// ---------------- zero small accumulators ------------------------------------
__global__ void zero_kernel() {
    int i = blockIdx.x * blockDim.x + threadIdx.x;
    if (i < NNODES)      g_deg[i] = 0;
    if (i < NGRAPH * 64) g_pool[i] = 0.f;
    if (i < NGRAPH)      g_cnt[i]  = 0.f;
}

// ---------------- CSR build ---------------------------------------------------
__global__ void hist_kernel(const void* __restrict__ ei, int E) {
    int e = blockIdx.x * blockDim.x + threadIdx.x;
    if (e >= E) return;
    int d = g_idx64 ? (int)((const long long*)ei)[E + e]
                    : ((const int*)ei)[E + e];
    atomicAdd(&g_deg[d], 1);
}

__global__ void scan_kernel() {
    __shared__ int ssum[1024];
    const int T = 1024, CH = (NNODES + T - 1) / T;   // 49
    int t = threadIdx.x;
    int base = t * CH;
    int s = 0;
    for (int i = 0; i < CH; i++) {
        int idx = base + i;
        if (idx < NNODES) s += g_deg[idx];
    }
    ssum[t] = s;
    __syncthreads();
    for (int off = 1; off < T; off <<= 1) {
        int v = (t >= off) ? ssum[t - off] : 0;
        __syncthreads();
        ssum[t] += v;
        __syncthreads();
    }
    int run = (t == 0) ? 0 : ssum[t - 1];
    for (int i = 0; i < CH; i++) {
        int idx = base + i;
        if (idx < NNODES) {
            g_rowstart[idx] = run;
            g_cursor[idx]   = run;
            run += g_deg[idx];
        }
    }
    if (t == T - 1) g_rowstart[NNODES] = run;
}

__global__ void scatter_kernel(const void* __restrict__ ei, int E) {
    int e = blockIdx.x * blockDim.x + threadIdx.x;
    if (e >= E) return;
    int s, d;
    if (g_idx64) {
        const long long* p = (const long long*)ei;
        s = (int)p[e]; d = (int)p[E + e];
    } else {
        const int* p = (const int*)ei;
        s = p[e]; d = p[E + e];
    }
    int pos = atomicAdd(&g_cursor[d], 1);
    g_csr_src[pos] = s;
}

// ---------------- dual-weight GEMM: C[M x 2*NHALF] = A[M x 128] @ [WL|WR] ----
__global__ void gemm_dual(const float* __restrict__ A,
                          const float* __restrict__ WL,
                          const float* __restrict__ WR,
                          float* __restrict__ C,
                          int M, int NHALF, int NN) {
    __shared__ float As[16][64];
    __shared__ float Bs[16][64];
    const int t  = threadIdx.x;
    const int tx = t & 15, ty = t >> 4;
    const int rowBase = blockIdx.y << 6;
    const int colTile = blockIdx.x << 6;

    const float* W;
    int colBase;
    if (colTile >= NHALF) { W = WR; colBase = colTile - NHALF; }
    else                  { W = WL; colBase = colTile; }

    const int arow = t >> 2, ak4 = (t & 3) << 2;
    const int brow = t >> 4, bc4 = (t & 15) << 2;

    float acc[4][4];
    #pragma unroll
    for (int i = 0; i < 4; i++)
        #pragma unroll
        for (int j = 0; j < 4; j++) acc[i][j] = 0.f;

    const int grow = rowBase + arow;
    const bool aval = grow < M;
    const float* Arow = A + (long)grow * FIN;

    for (int k0 = 0; k0 < FIN; k0 += 16) {
        float4 av = aval ? *(const float4*)(Arow + k0 + ak4)
                         : make_float4(0.f, 0.f, 0.f, 0.f);
        As[ak4 + 0][arow] = av.x;
        As[ak4 + 1][arow] = av.y;
        As[ak4 + 2][arow] = av.z;
        As[ak4 + 3][arow] = av.w;
        *(float4*)&Bs[brow][bc4] =
            *(const float4*)(W + (long)(k0 + brow) * NHALF + colBase + bc4);
        __syncthreads();
        #pragma unroll
        for (int k = 0; k < 16; k++) {
            float4 a = *(const float4*)&As[k][ty << 2];
            float4 b = *(const float4*)&Bs[k][tx << 2];
            acc[0][0] += a.x * b.x; acc[0][1] += a.x * b.y;
            acc[0][2] += a.x * b.z; acc[0][3] += a.x * b.w;
            acc[1][0] += a.y * b.x; acc[1][1] += a.y * b.y;
            acc[1][2] += a.y * b.z; acc[1][3] += a.y * b.w;
            acc[2][0] += a.z * b.x; acc[2][1] += a.z * b.y;
            acc[2][2] += a.z * b.z; acc[2][3] += a.z * b.w;
            acc[3][0] += a.w * b.x; acc[3][1] += a.w * b.y;
            acc[3][2] += a.w * b.z; acc[3][3] += a.w * b.w;
        }
        __syncthreads();
    }
    #pragma unroll
    for (int i = 0; i < 4; i++) {
        int r = rowBase + (ty << 2) + i;
        if (r < M) {
            float4 v = make_float4(acc[i][0], acc[i][1], acc[i][2], acc[i][3]);
            *(float4*)&C[(long)r * NN + colTile + (tx << 2)] = v;
        }
    }
}

// ---------------- conv1: warp/node gather aggregation + softmax + ELU --------
__global__ void conv1_kernel(const float* __restrict__ b1,
                             const float* __restrict__ att) {
    int w = (blockIdx.x * blockDim.x + threadIdx.x) >> 5;
    if (w >= NNODES) return;
    int lane = threadIdx.x & 31, c4 = lane << 2;

    float4 av = *(const float4*)&att[c4];
    float4 xr = *(const float4*)&g_xlr1[w * 256 + 128 + c4];
    float4 bb = *(const float4*)&b1[c4];

    float4 acc = make_float4(0.f, 0.f, 0.f, 0.f);
    float den = 0.f;

    int rs = g_rowstart[w], re = g_rowstart[w + 1];
    for (int e = rs - 1; e < re; e++) {        // e == rs-1 -> self loop
        int s = (e < rs) ? w : g_csr_src[e];
        float4 a = *(const float4*)&g_xlr1[s * 256 + c4];
        float sc = lrelu(a.x + xr.x) * av.x + lrelu(a.y + xr.y) * av.y +
                   lrelu(a.z + xr.z) * av.z + lrelu(a.w + xr.w) * av.w;
        sc += __shfl_xor_sync(0xffffffffu, sc, 8);
        sc += __shfl_xor_sync(0xffffffffu, sc, 4);
        sc += __shfl_xor_sync(0xffffffffu, sc, 2);
        sc += __shfl_xor_sync(0xffffffffu, sc, 1);
        float p = expf(sc);
        acc.x += p * a.x; acc.y += p * a.y;
        acc.z += p * a.z; acc.w += p * a.w;
        den += p;
    }
    float inv = 1.f / den;
    float4 h;
    h.x = elu(acc.x * inv + bb.x);
    h.y = elu(acc.y * inv + bb.y);
    h.z = elu(acc.z * inv + bb.z);
    h.w = elu(acc.w * inv + bb.w);
    *(float4*)&g_h1[w * 128 + c4] = h;
}

// ---------------- conv2: 16 lanes/node, + mean-pool scatter ------------------
__global__ void conv2_kernel(const float* __restrict__ b2,
                             const float* __restrict__ att,
                             const void* __restrict__ batch) {
    int idx = blockIdx.x * blockDim.x + threadIdx.x;
    int n = idx >> 4;
    if (n >= NNODES) return;
    int l = threadIdx.x & 15, c4 = l << 2;
    unsigned gmask = 0xFFFFu << (threadIdx.x & 16);

    float4 av = *(const float4*)&att[c4];
    float4 xr = *(const float4*)&g_xlr2[n * 128 + 64 + c4];
    float4 bb = *(const float4*)&b2[c4];

    float4 acc = make_float4(0.f, 0.f, 0.f, 0.f);
    float den = 0.f;

    int rs = g_rowstart[n], re = g_rowstart[n + 1];
    for (int e = rs - 1; e < re; e++) {
        int s = (e < rs) ? n : g_csr_src[e];
        float4 a = *(const float4*)&g_xlr2[s * 128 + c4];
        float sc = lrelu(a.x + xr.x) * av.x + lrelu(a.y + xr.y) * av.y +
                   lrelu(a.z + xr.z) * av.z + lrelu(a.w + xr.w) * av.w;
        sc += __shfl_xor_sync(gmask, sc, 8);
        sc += __shfl_xor_sync(gmask, sc, 4);
        sc += __shfl_xor_sync(gmask, sc, 2);
        sc += __shfl_xor_sync(gmask, sc, 1);
        float p = expf(sc);
        acc.x += p * a.x; acc.y += p * a.y;
        acc.z += p * a.z; acc.w += p * a.w;
        den += p;
    }
    float inv = 1.f / den;
    float4 h;
    h.x = elu(acc.x * inv + bb.x);
    h.y = elu(acc.y * inv + bb.y);
    h.z = elu(acc.z * inv + bb.z);
    h.w = elu(acc.w * inv + bb.w);

    int gph = g_idx64 ? (int)((const long long*)batch)[n]
                      : ((const int*)batch)[n];
    red_add4(&g_pool[gph * 64 + c4], h);
    if (l == 0) atomicAdd(&g_cnt[gph], 1.0f);
}

// ---------------- final: out = (pool/cnt) @ Wlin + blin ----------------------
__global__ void final_kernel(const float* __restrict__ Wlin,
                             const float* __restrict__ blin,
                             float* __restrict__ out) {
    int t = threadIdx.x;
    if (t >= NGRAPH * NCLS) return;
    int g = t / NCLS, j = t - g * NCLS;
    float inv = 1.f / fmaxf(g_cnt[g], 1.f);
    float s = 0.f;
    #pragma unroll
    for (int c = 0; c < 64; c++) s += g_pool[g * 64 + c] * Wlin[c * NCLS + j];
    out[t] = s * inv + blin[j];
}

// ---------------- launch ------------------------------------------------------
extern "C" void kernel_launch(void* const* d_in, const int* in_sizes, int n_in,
                              void* d_out, int out_size) {
    const float* x    = (const float*)d_in[0];
    const void*  ei   = d_in[1];
    const void*  bat  = d_in[2];
    const float* Wl1  = (const float*)d_in[3];
    const float* Wr1  = (const float*)d_in[4];
    const float* att1 = (const float*)d_in[5];
    const float* b1   = (const float*)d_in[6];
    const float* Wl2  = (const float*)d_in[7];
    const float* Wr2  = (const float*)d_in[8];
    const float* att2 = (const float*)d_in[9];
    const float* b2   = (const float*)d_in[10];
    const float* Wlin = (const float*)d_in[11];
    const float* blin = (const float*)d_in[12];
    float* out = (float*)d_out;

    int Nn = in_sizes[0] / 128;   // 50000
    int E  = in_sizes[1] / 2;     // 600000

    float *p_xlr1, *p_xlr2, *p_h1;
    cudaGetSymbolAddress((void**)&p_xlr1, g_xlr1);
    cudaGetSymbolAddress((void**)&p_xlr2, g_xlr2);
    cudaGetSymbolAddress((void**)&p_h1,   g_h1);

    detect_idx_kernel<<<1, 32>>>(ei);
    zero_kernel<<<(Nn + 255) / 256, 256>>>();
    hist_kernel<<<(E + 255) / 256, 256>>>(ei, E);
    scan_kernel<<<1, 1024>>>();
    scatter_kernel<<<(E + 255) / 256, 256>>>(ei, E);

    dim3 g1(4, (Nn + 63) / 64);
    gemm_dual<<<g1, 256>>>(x, Wl1, Wr1, p_xlr1, Nn, 128, 256);
    conv1_kernel<<<(Nn * 32 + 255) / 256, 256>>>(b1, att1);

    dim3 g2(2, (Nn + 63) / 64);
    gemm_dual<<<g2, 256>>>(p_h1, Wl2, Wr2, p_xlr2, Nn, 64, 128);
    conv2_kernel<<<(Nn * 16 + 255) / 256, 256>>>(b2, att2, bat);

    final_kernel<<<1, 640>>>(Wlin, blin, out);
}

// round 3
// speedup vs baseline: 1.2417x; 1.2417x over previous
#include <cuda_runtime.h>

#define NNODES 50000
#define NGRAPH 64
#define FIN    128
#define NCLS   10
#define MAXE   600000
#define NBLK   ((NNODES + 255) / 256)   // 196 scan blocks

// ---------------- scratch (static device arrays) -----------------------------
__device__ float g_xlr1[NNODES * 256];   // conv1: [xl(128) | xr(128)]
__device__ float g_h1  [NNODES * 128];   // conv1 output (post-ELU)
__device__ float g_xlr2[NNODES * 128];   // conv2: [xl(64) | xr(64)]
__device__ float g_pool[NGRAPH * 64];
__device__ float g_cnt [NGRAPH];
__device__ int   g_idx64;

__device__ int   g_deg     [NNODES];
__device__ int   g_rowstart[NNODES + 1];
__device__ int   g_cursor  [NNODES];
__device__ int   g_csr_src [MAXE];
__device__ int   g_bsum    [NBLK];
__device__ int   g_boff    [NBLK];

// ---------------- helpers -----------------------------------------------------
__device__ __forceinline__ void red_add4(float* p, float4 v) {
    asm volatile("red.global.add.v4.f32 [%0], {%1,%2,%3,%4};"
                 :: "l"(p), "f"(v.x), "f"(v.y), "f"(v.z), "f"(v.w) : "memory");
}
__device__ __forceinline__ float lrelu(float v) { return v > 0.f ? v : 0.2f * v; }
__device__ __forceinline__ float elu(float v)   { return v > 0.f ? v : expm1f(v); }

// ---------------- dtype detection --------------------------------------------
__global__ void detect_idx_kernel(const void* ei) {
    if (threadIdx.x == 0) {
        const long long* p = (const long long*)ei;
        int ok = 1;
        for (int i = 0; i < 16; i++) {
            long long v = p[i];
            if (v < 0 || v >= NNODES) ok = 0;
        }
        g_idx64 = ok;
    }
}

// ---------------- zero small accumulators ------------------------------------
__global__ void zero_kernel() {
    int i = blockIdx.x * blockDim.x + threadIdx.x;
    if (i < NNODES)      g_deg[i] = 0;
    if (i < NGRAPH * 64) g_pool[i] = 0.f;
    if (i < NGRAPH)      g_cnt[i]  = 0.f;
}

// ---------------- CSR build ---------------------------------------------------
__global__ void hist_kernel(const void* __restrict__ ei, int E) {
    int e = blockIdx.x * blockDim.x + threadIdx.x;
    if (e >= E) return;
    int d = g_idx64 ? (int)((const long long*)ei)[E + e]
                    : ((const int*)ei)[E + e];
    atomicAdd(&g_deg[d], 1);
}

// pass 1: per-block sums of deg
__global__ void scan1_kernel() {
    int i = blockIdx.x * 256 + threadIdx.x;
    int v = (i < NNODES) ? g_deg[i] : 0;
    int s = v;
    #pragma unroll
    for (int off = 16; off; off >>= 1) s += __shfl_xor_sync(~0u, s, off);
    __shared__ int ws[8];
    if ((threadIdx.x & 31) == 0) ws[threadIdx.x >> 5] = s;
    __syncthreads();
    if (threadIdx.x == 0) {
        int t = 0;
        #pragma unroll
        for (int w = 0; w < 8; w++) t += ws[w];
        g_bsum[blockIdx.x] = t;
    }
}

// pass 2: exclusive scan of the 196 block sums (one block)
__global__ void scan2_kernel() {
    __shared__ int sh[256];
    int t = threadIdx.x;
    int v = (t < NBLK) ? g_bsum[t] : 0;
    sh[t] = v;
    __syncthreads();
    for (int off = 1; off < 256; off <<= 1) {
        int u = (t >= off) ? sh[t - off] : 0;
        __syncthreads();
        sh[t] += u;
        __syncthreads();
    }
    if (t < NBLK) g_boff[t] = sh[t] - v;
}

// pass 3: per-block exclusive scan + block offset -> rowstart/cursor
__global__ void scan3_kernel() {
    int i = blockIdx.x * 256 + threadIdx.x;
    int lane = threadIdx.x & 31, warp = threadIdx.x >> 5;
    int v = (i < NNODES) ? g_deg[i] : 0;
    int x = v;
    #pragma unroll
    for (int off = 1; off < 32; off <<= 1) {
        int y = __shfl_up_sync(~0u, x, off);
        if (lane >= off) x += y;
    }
    __shared__ int ws[8];
    if (lane == 31) ws[warp] = x;
    __syncthreads();
    if (threadIdx.x == 0) {
        int run = 0;
        #pragma unroll
        for (int w = 0; w < 8; w++) { int tmp = ws[w]; ws[w] = run; run += tmp; }
    }
    __syncthreads();
    int incl = x + ws[warp];
    int base = g_boff[blockIdx.x];
    if (i < NNODES) {
        int rs = base + incl - v;
        g_rowstart[i] = rs;
        g_cursor[i]   = rs;
        if (i == NNODES - 1) g_rowstart[NNODES] = base + incl;
    }
}

__global__ void scatter_kernel(const void* __restrict__ ei, int E) {
    int e = blockIdx.x * blockDim.x + threadIdx.x;
    if (e >= E) return;
    int s, d;
    if (g_idx64) {
        const long long* p = (const long long*)ei;
        s = (int)p[e]; d = (int)p[E + e];
    } else {
        const int* p = (const int*)ei;
        s = p[e]; d = p[E + e];
    }
    int pos = atomicAdd(&g_cursor[d], 1);
    g_csr_src[pos] = s;
}

// ---------------- dual-weight GEMM: C[M x 2*NHALF] = A[M x 128] @ [WL|WR] ----
__global__ void gemm_dual(const float* __restrict__ A,
                          const float* __restrict__ WL,
                          const float* __restrict__ WR,
                          float* __restrict__ C,
                          int M, int NHALF, int NN) {
    __shared__ float As[16][64];
    __shared__ float Bs[16][64];
    const int t  = threadIdx.x;
    const int tx = t & 15, ty = t >> 4;
    const int rowBase = blockIdx.y << 6;
    const int colTile = blockIdx.x << 6;

    const float* W;
    int colBase;
    if (colTile >= NHALF) { W = WR; colBase = colTile - NHALF; }
    else                  { W = WL; colBase = colTile; }

    const int arow = t >> 2, ak4 = (t & 3) << 2;
    const int brow = t >> 4, bc4 = (t & 15) << 2;

    float acc[4][4];
    #pragma unroll
    for (int i = 0; i < 4; i++)
        #pragma unroll
        for (int j = 0; j < 4; j++) acc[i][j] = 0.f;

    const int grow = rowBase + arow;
    const bool aval = grow < M;
    const float* Arow = A + (long)grow * FIN;

    for (int k0 = 0; k0 < FIN; k0 += 16) {
        float4 av = aval ? *(const float4*)(Arow + k0 + ak4)
                         : make_float4(0.f, 0.f, 0.f, 0.f);
        As[ak4 + 0][arow] = av.x;
        As[ak4 + 1][arow] = av.y;
        As[ak4 + 2][arow] = av.z;
        As[ak4 + 3][arow] = av.w;
        *(float4*)&Bs[brow][bc4] =
            *(const float4*)(W + (long)(k0 + brow) * NHALF + colBase + bc4);
        __syncthreads();
        #pragma unroll
        for (int k = 0; k < 16; k++) {
            float4 a = *(const float4*)&As[k][ty << 2];
            float4 b = *(const float4*)&Bs[k][tx << 2];
            acc[0][0] += a.x * b.x; acc[0][1] += a.x * b.y;
            acc[0][2] += a.x * b.z; acc[0][3] += a.x * b.w;
            acc[1][0] += a.y * b.x; acc[1][1] += a.y * b.y;
            acc[1][2] += a.y * b.z; acc[1][3] += a.y * b.w;
            acc[2][0] += a.z * b.x; acc[2][1] += a.z * b.y;
            acc[2][2] += a.z * b.z; acc[2][3] += a.z * b.w;
            acc[3][0] += a.w * b.x; acc[3][1] += a.w * b.y;
            acc[3][2] += a.w * b.z; acc[3][3] += a.w * b.w;
        }
        __syncthreads();
    }
    #pragma unroll
    for (int i = 0; i < 4; i++) {
        int r = rowBase + (ty << 2) + i;
        if (r < M) {
            float4 v = make_float4(acc[i][0], acc[i][1], acc[i][2], acc[i][3]);
            *(float4*)&C[(long)r * NN + colTile + (tx << 2)] = v;
        }
    }
}

// ---------------- conv1: warp/node gather aggregation + softmax + ELU --------
__global__ void conv1_kernel(const float* __restrict__ b1,
                             const float* __restrict__ att) {
    int w = (blockIdx.x * blockDim.x + threadIdx.x) >> 5;
    if (w >= NNODES) return;
    int lane = threadIdx.x & 31, c4 = lane << 2;

    float4 av = *(const float4*)&att[c4];
    float4 xr = *(const float4*)&g_xlr1[w * 256 + 128 + c4];
    float4 bb = *(const float4*)&b1[c4];

    float4 acc = make_float4(0.f, 0.f, 0.f, 0.f);
    float den = 0.f;

    int rs = g_rowstart[w], re = g_rowstart[w + 1];
    for (int e = rs - 1; e < re; e++) {        // e == rs-1 -> self loop
        int s = (e < rs) ? w : g_csr_src[e];
        float4 a = *(const float4*)&g_xlr1[s * 256 + c4];
        float sc = lrelu(a.x + xr.x) * av.x + lrelu(a.y + xr.y) * av.y +
                   lrelu(a.z + xr.z) * av.z + lrelu(a.w + xr.w) * av.w;
        sc += __shfl_xor_sync(0xffffffffu, sc, 8);
        sc += __shfl_xor_sync(0xffffffffu, sc, 4);
        sc += __shfl_xor_sync(0xffffffffu, sc, 2);
        sc += __shfl_xor_sync(0xffffffffu, sc, 1);
        float p = expf(sc);
        acc.x += p * a.x; acc.y += p * a.y;
        acc.z += p * a.z; acc.w += p * a.w;
        den += p;
    }
    float inv = 1.f / den;
    float4 h;
    h.x = elu(acc.x * inv + bb.x);
    h.y = elu(acc.y * inv + bb.y);
    h.z = elu(acc.z * inv + bb.z);
    h.w = elu(acc.w * inv + bb.w);
    *(float4*)&g_h1[w * 128 + c4] = h;
}

// ---------------- conv2: 16 lanes/node, + mean-pool scatter ------------------
__global__ void conv2_kernel(const float* __restrict__ b2,
                             const float* __restrict__ att,
                             const void* __restrict__ batch) {
    int idx = blockIdx.x * blockDim.x + threadIdx.x;
    int n = idx >> 4;
    if (n >= NNODES) return;
    int l = threadIdx.x & 15, c4 = l << 2;
    unsigned gmask = 0xFFFFu << (threadIdx.x & 16);

    float4 av = *(const float4*)&att[c4];
    float4 xr = *(const float4*)&g_xlr2[n * 128 + 64 + c4];
    float4 bb = *(const float4*)&b2[c4];

    float4 acc = make_float4(0.f, 0.f, 0.f, 0.f);
    float den = 0.f;

    int rs = g_rowstart[n], re = g_rowstart[n + 1];
    for (int e = rs - 1; e < re; e++) {
        int s = (e < rs) ? n : g_csr_src[e];
        float4 a = *(const float4*)&g_xlr2[s * 128 + c4];
        float sc = lrelu(a.x + xr.x) * av.x + lrelu(a.y + xr.y) * av.y +
                   lrelu(a.z + xr.z) * av.z + lrelu(a.w + xr.w) * av.w;
        sc += __shfl_xor_sync(gmask, sc, 8);
        sc += __shfl_xor_sync(gmask, sc, 4);
        sc += __shfl_xor_sync(gmask, sc, 2);
        sc += __shfl_xor_sync(gmask, sc, 1);
        float p = expf(sc);
        acc.x += p * a.x; acc.y += p * a.y;
        acc.z += p * a.z; acc.w += p * a.w;
        den += p;
    }
    float inv = 1.f / den;
    float4 h;
    h.x = elu(acc.x * inv + bb.x);
    h.y = elu(acc.y * inv + bb.y);
    h.z = elu(acc.z * inv + bb.z);
    h.w = elu(acc.w * inv + bb.w);

    int gph = g_idx64 ? (int)((const long long*)batch)[n]
                      : ((const int*)batch)[n];
    red_add4(&g_pool[gph * 64 + c4], h);
    if (l == 0) atomicAdd(&g_cnt[gph], 1.0f);
}

// ---------------- final: out = (pool/cnt) @ Wlin + blin ----------------------
__global__ void final_kernel(const float* __restrict__ Wlin,
                             const float* __restrict__ blin,
                             float* __restrict__ out) {
    int t = threadIdx.x;
    if (t >= NGRAPH * NCLS) return;
    int g = t / NCLS, j = t - g * NCLS;
    float inv = 1.f / fmaxf(g_cnt[g], 1.f);
    float s = 0.f;
    #pragma unroll
    for (int c = 0; c < 64; c++) s += g_pool[g * 64 + c] * Wlin[c * NCLS + j];
    out[t] = s * inv + blin[j];
}

// ---------------- launch ------------------------------------------------------
extern "C" void kernel_launch(void* const* d_in, const int* in_sizes, int n_in,
                              void* d_out, int out_size) {
    const float* x    = (const float*)d_in[0];
    const void*  ei   = d_in[1];
    const void*  bat  = d_in[2];
    const float* Wl1  = (const float*)d_in[3];
    const float* Wr1  = (const float*)d_in[4];
    const float* att1 = (const float*)d_in[5];
    const float* b1   = (const float*)d_in[6];
    const float* Wl2  = (const float*)d_in[7];
    const float* Wr2  = (const float*)d_in[8];
    const float* att2 = (const float*)d_in[9];
    const float* b2   = (const float*)d_in[10];
    const float* Wlin = (const float*)d_in[11];
    const float* blin = (const float*)d_in[12];
    float* out = (float*)d_out;

    int Nn = in_sizes[0] / 128;   // 50000
    int E  = in_sizes[1] / 2;     // 600000

    float *p_xlr1, *p_xlr2, *p_h1;
    cudaGetSymbolAddress((void**)&p_xlr1, g_xlr1);
    cudaGetSymbolAddress((void**)&p_xlr2, g_xlr2);
    cudaGetSymbolAddress((void**)&p_h1,   g_h1);

    detect_idx_kernel<<<1, 32>>>(ei);
    zero_kernel<<<(Nn + 255) / 256, 256>>>();
    hist_kernel<<<(E + 255) / 256, 256>>>(ei, E);
    scan1_kernel<<<NBLK, 256>>>();
    scan2_kernel<<<1, 256>>>();
    scan3_kernel<<<NBLK, 256>>>();
    scatter_kernel<<<(E + 255) / 256, 256>>>(ei, E);

    dim3 g1(4, (Nn + 63) / 64);
    gemm_dual<<<g1, 256>>>(x, Wl1, Wr1, p_xlr1, Nn, 128, 256);
    conv1_kernel<<<(Nn * 32 + 255) / 256, 256>>>(b1, att1);

    dim3 g2(2, (Nn + 63) / 64);
    gemm_dual<<<g2, 256>>>(p_h1, Wl2, Wr2, p_xlr2, Nn, 64, 128);
    conv2_kernel<<<(Nn * 16 + 255) / 256, 256>>>(b2, att2, bat);

    final_kernel<<<1, 640>>>(Wlin, blin, out);
}

// round 4
// speedup vs baseline: 1.3537x; 1.0902x over previous
#include <cuda_runtime.h>

#define NNODES 50000
#define NGRAPH 64
#define FIN    128
#define NCLS   10
#define MAXE   600000
#define NBLK   ((NNODES + 255) / 256)   // 196 scan blocks

// ---------------- scratch (static device arrays) -----------------------------
__device__ float g_xlr1[NNODES * 256];   // conv1: [xl(128) | xr(128)]
__device__ float g_h1  [NNODES * 128];   // conv1 output (post-ELU)
__device__ float g_xlr2[NNODES * 128];   // conv2: [xl(64) | xr(64)]
__device__ float g_pool[NGRAPH * 64];
__device__ float g_cnt [NGRAPH];
__device__ int   g_idx64;

__device__ int   g_deg     [NNODES];
__device__ int   g_rowstart[NNODES + 1];
__device__ int   g_cursor  [NNODES];
__device__ int   g_csr_src [MAXE];
__device__ int   g_bsum    [NBLK];
__device__ int   g_boff    [NBLK];

// ---------------- helpers -----------------------------------------------------
__device__ __forceinline__ void red_add4(float* p, float4 v) {
    asm volatile("red.global.add.v4.f32 [%0], {%1,%2,%3,%4};"
                 :: "l"(p), "f"(v.x), "f"(v.y), "f"(v.z), "f"(v.w) : "memory");
}
__device__ __forceinline__ float lrelu(float v) { return v > 0.f ? v : 0.2f * v; }
__device__ __forceinline__ float elu(float v)   { return v > 0.f ? v : expm1f(v); }

__device__ __forceinline__ unsigned f2tf(float f) {
    unsigned r;
    asm("cvt.rna.tf32.f32 %0, %1;" : "=r"(r) : "f"(f));
    return r;
}
__device__ __forceinline__ void tfsplit(float f, unsigned& hi, unsigned& lo) {
    hi = f2tf(f);
    lo = f2tf(f - __uint_as_float(hi));
}
__device__ __forceinline__ void mma_tf32(float* c, const unsigned* a, const unsigned* b) {
    asm volatile(
        "mma.sync.aligned.m16n8k8.row.col.f32.tf32.tf32.f32 "
        "{%0,%1,%2,%3}, {%4,%5,%6,%7}, {%8,%9}, {%0,%1,%2,%3};"
        : "+f"(c[0]), "+f"(c[1]), "+f"(c[2]), "+f"(c[3])
        : "r"(a[0]), "r"(a[1]), "r"(a[2]), "r"(a[3]), "r"(b[0]), "r"(b[1]));
}

// ---------------- dtype detection --------------------------------------------
__global__ void detect_idx_kernel(const void* ei) {
    if (threadIdx.x == 0) {
        const long long* p = (const long long*)ei;
        int ok = 1;
        for (int i = 0; i < 16; i++) {
            long long v = p[i];
            if (v < 0 || v >= NNODES) ok = 0;
        }
        g_idx64 = ok;
    }
}

// ---------------- zero small accumulators ------------------------------------
__global__ void zero_kernel() {
    int i = blockIdx.x * blockDim.x + threadIdx.x;
    if (i < NNODES)      g_deg[i] = 0;
    if (i < NGRAPH * 64) g_pool[i] = 0.f;
    if (i < NGRAPH)      g_cnt[i]  = 0.f;
}

// ---------------- CSR build ---------------------------------------------------
__global__ void hist_kernel(const void* __restrict__ ei, int E) {
    int e = blockIdx.x * blockDim.x + threadIdx.x;
    if (e >= E) return;
    int d = g_idx64 ? (int)((const long long*)ei)[E + e]
                    : ((const int*)ei)[E + e];
    atomicAdd(&g_deg[d], 1);
}

__global__ void scan1_kernel() {
    int i = blockIdx.x * 256 + threadIdx.x;
    int v = (i < NNODES) ? g_deg[i] : 0;
    int s = v;
    #pragma unroll
    for (int off = 16; off; off >>= 1) s += __shfl_xor_sync(~0u, s, off);
    __shared__ int ws[8];
    if ((threadIdx.x & 31) == 0) ws[threadIdx.x >> 5] = s;
    __syncthreads();
    if (threadIdx.x == 0) {
        int t = 0;
        #pragma unroll
        for (int w = 0; w < 8; w++) t += ws[w];
        g_bsum[blockIdx.x] = t;
    }
}

__global__ void scan2_kernel() {
    __shared__ int sh[256];
    int t = threadIdx.x;
    int v = (t < NBLK) ? g_bsum[t] : 0;
    sh[t] = v;
    __syncthreads();
    for (int off = 1; off < 256; off <<= 1) {
        int u = (t >= off) ? sh[t - off] : 0;
        __syncthreads();
        sh[t] += u;
        __syncthreads();
    }
    if (t < NBLK) g_boff[t] = sh[t] - v;
}

__global__ void scan3_kernel() {
    int i = blockIdx.x * 256 + threadIdx.x;
    int lane = threadIdx.x & 31, warp = threadIdx.x >> 5;
    int v = (i < NNODES) ? g_deg[i] : 0;
    int x = v;
    #pragma unroll
    for (int off = 1; off < 32; off <<= 1) {
        int y = __shfl_up_sync(~0u, x, off);
        if (lane >= off) x += y;
    }
    __shared__ int ws[8];
    if (lane == 31) ws[warp] = x;
    __syncthreads();
    if (threadIdx.x == 0) {
        int run = 0;
        #pragma unroll
        for (int w = 0; w < 8; w++) { int tmp = ws[w]; ws[w] = run; run += tmp; }
    }
    __syncthreads();
    int incl = x + ws[warp];
    int base = g_boff[blockIdx.x];
    if (i < NNODES) {
        int rs = base + incl - v;
        g_rowstart[i] = rs;
        g_cursor[i]   = rs;
        if (i == NNODES - 1) g_rowstart[NNODES] = base + incl;
    }
}

__global__ void scatter_kernel(const void* __restrict__ ei, int E) {
    int e = blockIdx.x * blockDim.x + threadIdx.x;
    if (e >= E) return;
    int s, d;
    if (g_idx64) {
        const long long* p = (const long long*)ei;
        s = (int)p[e]; d = (int)p[E + e];
    } else {
        const int* p = (const int*)ei;
        s = p[e]; d = p[E + e];
    }
    int pos = atomicAdd(&g_cursor[d], 1);
    g_csr_src[pos] = s;
}

// ---------------- tensor-core dual-weight GEMM -------------------------------
// C[M x NN] tile 128x64 per block; W = (colTile < NHALF) ? WL : WR.
// tf32 mma m16n8k8 with hi/lo split for fp32-level accuracy.
#define APAD 36
#define BPAD 68
__global__ __launch_bounds__(256) void gemm_tc(
        const float* __restrict__ A,
        const float* __restrict__ WL,
        const float* __restrict__ WR,
        float* __restrict__ C,
        int M, int NHALF, int NN) {
    __shared__ float As[128][APAD];
    __shared__ float Bs[32][BPAD];

    const int t = threadIdx.x;
    const int lane = t & 31, g = lane >> 2, tig = lane & 3;
    const int w = t >> 5, wr = w & 3, wc = w >> 2;   // warp 32x32 tile
    const int rowBase = blockIdx.y << 7;
    const int colTile = blockIdx.x << 6;

    const float* W;
    int colBase;
    if (colTile >= NHALF) { W = WR; colBase = colTile - NHALF; }
    else                  { W = WL; colBase = colTile; }

    float acc[2][4][4];
    #pragma unroll
    for (int mi = 0; mi < 2; mi++)
        #pragma unroll
        for (int ni = 0; ni < 4; ni++)
            #pragma unroll
            for (int j = 0; j < 4; j++) acc[mi][ni][j] = 0.f;

    const int arow = t >> 3, ac4 = (t & 7) << 2;   // A: 32 rows/iter x 8 f4
    for (int k0 = 0; k0 < FIN; k0 += 32) {
        #pragma unroll
        for (int r = 0; r < 4; r++) {
            int row = arow + r * 32;
            int grow = rowBase + row;
            if (grow >= M) grow = M - 1;
            float4 v = *(const float4*)&A[(long)grow * FIN + k0 + ac4];
            *(float4*)&As[row][ac4] = v;
        }
        #pragma unroll
        for (int j = 0; j < 2; j++) {
            int i = t + j * 256;
            int brow = i >> 4, bc4 = (i & 15) << 2;
            float4 v = *(const float4*)&W[(long)(k0 + brow) * NHALF + colBase + bc4];
            *(float4*)&Bs[brow][bc4] = v;
        }
        __syncthreads();

        #pragma unroll
        for (int kk = 0; kk < 32; kk += 8) {
            unsigned ah[2][4], al[2][4], bh[4][2], bl[4][2];
            #pragma unroll
            for (int mi = 0; mi < 2; mi++) {
                int rb = wr * 32 + mi * 16;
                tfsplit(As[rb + g    ][kk + tig    ], ah[mi][0], al[mi][0]);
                tfsplit(As[rb + 8 + g][kk + tig    ], ah[mi][1], al[mi][1]);
                tfsplit(As[rb + g    ][kk + 4 + tig], ah[mi][2], al[mi][2]);
                tfsplit(As[rb + 8 + g][kk + 4 + tig], ah[mi][3], al[mi][3]);
            }
            #pragma unroll
            for (int ni = 0; ni < 4; ni++) {
                int col = wc * 32 + ni * 8 + g;
                tfsplit(Bs[kk + tig    ][col], bh[ni][0], bl[ni][0]);
                tfsplit(Bs[kk + 4 + tig][col], bh[ni][1], bl[ni][1]);
            }
            #pragma unroll
            for (int mi = 0; mi < 2; mi++)
                #pragma unroll
                for (int ni = 0; ni < 4; ni++) {
                    mma_tf32(acc[mi][ni], ah[mi], bh[ni]);
                    mma_tf32(acc[mi][ni], ah[mi], bl[ni]);
                    mma_tf32(acc[mi][ni], al[mi], bh[ni]);
                }
        }
        __syncthreads();
    }

    // store C: c0,c1 -> (row, 2*tig), c2,c3 -> (row+8, 2*tig)
    #pragma unroll
    for (int mi = 0; mi < 2; mi++) {
        int row0 = rowBase + wr * 32 + mi * 16 + g;
        #pragma unroll
        for (int ni = 0; ni < 4; ni++) {
            int col = colTile + wc * 32 + ni * 8 + 2 * tig;
            if (row0 < M)
                *(float2*)&C[(long)row0 * NN + col] =
                    make_float2(acc[mi][ni][0], acc[mi][ni][1]);
            if (row0 + 8 < M)
                *(float2*)&C[(long)(row0 + 8) * NN + col] =
                    make_float2(acc[mi][ni][2], acc[mi][ni][3]);
        }
    }
}

// ---------------- conv1: warp/node gather aggregation + softmax + ELU --------
__global__ void conv1_kernel(const float* __restrict__ b1,
                             const float* __restrict__ att) {
    int w = (blockIdx.x * blockDim.x + threadIdx.x) >> 5;
    if (w >= NNODES) return;
    int lane = threadIdx.x & 31, c4 = lane << 2;

    float4 av = *(const float4*)&att[c4];
    float4 xr = *(const float4*)&g_xlr1[w * 256 + 128 + c4];
    float4 bb = *(const float4*)&b1[c4];

    float4 acc = make_float4(0.f, 0.f, 0.f, 0.f);
    float den = 0.f;

    int rs = g_rowstart[w], re = g_rowstart[w + 1];
    for (int e = rs - 1; e < re; e++) {        // e == rs-1 -> self loop
        int s = (e < rs) ? w : g_csr_src[e];
        float4 a = *(const float4*)&g_xlr1[s * 256 + c4];
        float sc = lrelu(a.x + xr.x) * av.x + lrelu(a.y + xr.y) * av.y +
                   lrelu(a.z + xr.z) * av.z + lrelu(a.w + xr.w) * av.w;
        sc += __shfl_xor_sync(0xffffffffu, sc, 8);
        sc += __shfl_xor_sync(0xffffffffu, sc, 4);
        sc += __shfl_xor_sync(0xffffffffu, sc, 2);
        sc += __shfl_xor_sync(0xffffffffu, sc, 1);
        float p = expf(sc);
        acc.x += p * a.x; acc.y += p * a.y;
        acc.z += p * a.z; acc.w += p * a.w;
        den += p;
    }
    float inv = 1.f / den;
    float4 h;
    h.x = elu(acc.x * inv + bb.x);
    h.y = elu(acc.y * inv + bb.y);
    h.z = elu(acc.z * inv + bb.z);
    h.w = elu(acc.w * inv + bb.w);
    *(float4*)&g_h1[w * 128 + c4] = h;
}

// ---------------- conv2: 16 lanes/node, + mean-pool scatter ------------------
__global__ void conv2_kernel(const float* __restrict__ b2,
                             const float* __restrict__ att,
                             const void* __restrict__ batch) {
    int idx = blockIdx.x * blockDim.x + threadIdx.x;
    int n = idx >> 4;
    if (n >= NNODES) return;
    int l = threadIdx.x & 15, c4 = l << 2;
    unsigned gmask = 0xFFFFu << (threadIdx.x & 16);

    float4 av = *(const float4*)&att[c4];
    float4 xr = *(const float4*)&g_xlr2[n * 128 + 64 + c4];
    float4 bb = *(const float4*)&b2[c4];

    float4 acc = make_float4(0.f, 0.f, 0.f, 0.f);
    float den = 0.f;

    int rs = g_rowstart[n], re = g_rowstart[n + 1];
    for (int e = rs - 1; e < re; e++) {
        int s = (e < rs) ? n : g_csr_src[e];
        float4 a = *(const float4*)&g_xlr2[s * 128 + c4];
        float sc = lrelu(a.x + xr.x) * av.x + lrelu(a.y + xr.y) * av.y +
                   lrelu(a.z + xr.z) * av.z + lrelu(a.w + xr.w) * av.w;
        sc += __shfl_xor_sync(gmask, sc, 8);
        sc += __shfl_xor_sync(gmask, sc, 4);
        sc += __shfl_xor_sync(gmask, sc, 2);
        sc += __shfl_xor_sync(gmask, sc, 1);
        float p = expf(sc);
        acc.x += p * a.x; acc.y += p * a.y;
        acc.z += p * a.z; acc.w += p * a.w;
        den += p;
    }
    float inv = 1.f / den;
    float4 h;
    h.x = elu(acc.x * inv + bb.x);
    h.y = elu(acc.y * inv + bb.y);
    h.z = elu(acc.z * inv + bb.z);
    h.w = elu(acc.w * inv + bb.w);

    int gph = g_idx64 ? (int)((const long long*)batch)[n]
                      : ((const int*)batch)[n];
    red_add4(&g_pool[gph * 64 + c4], h);
    if (l == 0) atomicAdd(&g_cnt[gph], 1.0f);
}

// ---------------- final: out = (pool/cnt) @ Wlin + blin ----------------------
__global__ void final_kernel(const float* __restrict__ Wlin,
                             const float* __restrict__ blin,
                             float* __restrict__ out) {
    int t = threadIdx.x;
    if (t >= NGRAPH * NCLS) return;
    int g = t / NCLS, j = t - g * NCLS;
    float inv = 1.f / fmaxf(g_cnt[g], 1.f);
    float s = 0.f;
    #pragma unroll
    for (int c = 0; c < 64; c++) s += g_pool[g * 64 + c] * Wlin[c * NCLS + j];
    out[t] = s * inv + blin[j];
}

// ---------------- launch ------------------------------------------------------
extern "C" void kernel_launch(void* const* d_in, const int* in_sizes, int n_in,
                              void* d_out, int out_size) {
    const float* x    = (const float*)d_in[0];
    const void*  ei   = d_in[1];
    const void*  bat  = d_in[2];
    const float* Wl1  = (const float*)d_in[3];
    const float* Wr1  = (const float*)d_in[4];
    const float* att1 = (const float*)d_in[5];
    const float* b1   = (const float*)d_in[6];
    const float* Wl2  = (const float*)d_in[7];
    const float* Wr2  = (const float*)d_in[8];
    const float* att2 = (const float*)d_in[9];
    const float* b2   = (const float*)d_in[10];
    const float* Wlin = (const float*)d_in[11];
    const float* blin = (const float*)d_in[12];
    float* out = (float*)d_out;

    int Nn = in_sizes[0] / 128;   // 50000
    int E  = in_sizes[1] / 2;     // 600000

    float *p_xlr1, *p_xlr2, *p_h1;
    cudaGetSymbolAddress((void**)&p_xlr1, g_xlr1);
    cudaGetSymbolAddress((void**)&p_xlr2, g_xlr2);
    cudaGetSymbolAddress((void**)&p_h1,   g_h1);

    detect_idx_kernel<<<1, 32>>>(ei);
    zero_kernel<<<(Nn + 255) / 256, 256>>>();
    hist_kernel<<<(E + 255) / 256, 256>>>(ei, E);
    scan1_kernel<<<NBLK, 256>>>();
    scan2_kernel<<<1, 256>>>();
    scan3_kernel<<<NBLK, 256>>>();
    scatter_kernel<<<(E + 255) / 256, 256>>>(ei, E);

    dim3 g1(4, (Nn + 127) / 128);
    gemm_tc<<<g1, 256>>>(x, Wl1, Wr1, p_xlr1, Nn, 128, 256);
    conv1_kernel<<<(Nn * 32 + 255) / 256, 256>>>(b1, att1);

    dim3 g2(2, (Nn + 127) / 128);
    gemm_tc<<<g2, 256>>>(p_h1, Wl2, Wr2, p_xlr2, Nn, 64, 128);
    conv2_kernel<<<(Nn * 16 + 255) / 256, 256>>>(b2, att2, bat);

    final_kernel<<<1, 640>>>(Wlin, blin, out);
}

// round 5
// speedup vs baseline: 1.3743x; 1.0152x over previous
#include <cuda_runtime.h>

#define NNODES 50000
#define NGRAPH 64
#define FIN    128
#define NCLS   10
#define MAXE   600000
#define NBLK   ((NNODES + 255) / 256)   // 196 scan blocks

// ---------------- scratch (static device arrays) -----------------------------
__device__ float g_xlr1[NNODES * 256];   // conv1: [xl(128) | xr(128)]
__device__ float g_h1  [NNODES * 128];   // conv1 output (post-ELU)
__device__ float g_xlr2[NNODES * 128];   // conv2: [xl(64) | xr(64)]
__device__ float g_pool[NGRAPH * 64];
__device__ float g_cnt [NGRAPH];
__device__ int   g_idx64;

__device__ int   g_deg     [NNODES];
__device__ int   g_rowstart[NNODES + 1];
__device__ int   g_cursor  [NNODES];
__device__ int   g_csr_src [MAXE];
__device__ int   g_bsum    [NBLK];
__device__ int   g_boff    [NBLK];

// ---------------- helpers -----------------------------------------------------
__device__ __forceinline__ void red_add4(float* p, float4 v) {
    asm volatile("red.global.add.v4.f32 [%0], {%1,%2,%3,%4};"
                 :: "l"(p), "f"(v.x), "f"(v.y), "f"(v.z), "f"(v.w) : "memory");
}
__device__ __forceinline__ float lrelu(float v) { return v > 0.f ? v : 0.2f * v; }
__device__ __forceinline__ float elu(float v)   { return v > 0.f ? v : expm1f(v); }

__device__ __forceinline__ unsigned f2tf(float f) {
    unsigned r;
    asm("cvt.rna.tf32.f32 %0, %1;" : "=r"(r) : "f"(f));
    return r;
}
__device__ __forceinline__ void tfsplit(float f, unsigned& hi, unsigned& lo) {
    hi = f2tf(f);
    lo = f2tf(f - __uint_as_float(hi));
}
__device__ __forceinline__ void mma_tf32(float* c, const unsigned* a, const unsigned* b) {
    asm volatile(
        "mma.sync.aligned.m16n8k8.row.col.f32.tf32.tf32.f32 "
        "{%0,%1,%2,%3}, {%4,%5,%6,%7}, {%8,%9}, {%0,%1,%2,%3};"
        : "+f"(c[0]), "+f"(c[1]), "+f"(c[2]), "+f"(c[3])
        : "r"(a[0]), "r"(a[1]), "r"(a[2]), "r"(a[3]), "r"(b[0]), "r"(b[1]));
}

// ---------------- dtype detection --------------------------------------------
__global__ void detect_idx_kernel(const void* ei) {
    if (threadIdx.x == 0) {
        const long long* p = (const long long*)ei;
        int ok = 1;
        for (int i = 0; i < 16; i++) {
            long long v = p[i];
            if (v < 0 || v >= NNODES) ok = 0;
        }
        g_idx64 = ok;
    }
}

// ---------------- zero small accumulators ------------------------------------
__global__ void zero_kernel() {
    int i = blockIdx.x * blockDim.x + threadIdx.x;
    if (i < NNODES)      g_deg[i] = 0;
    if (i < NGRAPH * 64) g_pool[i] = 0.f;
    if (i < NGRAPH)      g_cnt[i]  = 0.f;
}

// ---------------- CSR build ---------------------------------------------------
__global__ void hist_kernel(const void* __restrict__ ei, int E) {
    int e = blockIdx.x * blockDim.x + threadIdx.x;
    if (e >= E) return;
    int d = g_idx64 ? (int)((const long long*)ei)[E + e]
                    : ((const int*)ei)[E + e];
    atomicAdd(&g_deg[d], 1);
}

__global__ void scan1_kernel() {
    int i = blockIdx.x * 256 + threadIdx.x;
    int v = (i < NNODES) ? g_deg[i] : 0;
    int s = v;
    #pragma unroll
    for (int off = 16; off; off >>= 1) s += __shfl_xor_sync(~0u, s, off);
    __shared__ int ws[8];
    if ((threadIdx.x & 31) == 0) ws[threadIdx.x >> 5] = s;
    __syncthreads();
    if (threadIdx.x == 0) {
        int t = 0;
        #pragma unroll
        for (int w = 0; w < 8; w++) t += ws[w];
        g_bsum[blockIdx.x] = t;
    }
}

__global__ void scan2_kernel() {
    __shared__ int sh[256];
    int t = threadIdx.x;
    int v = (t < NBLK) ? g_bsum[t] : 0;
    sh[t] = v;
    __syncthreads();
    for (int off = 1; off < 256; off <<= 1) {
        int u = (t >= off) ? sh[t - off] : 0;
        __syncthreads();
        sh[t] += u;
        __syncthreads();
    }
    if (t < NBLK) g_boff[t] = sh[t] - v;
}

__global__ void scan3_kernel() {
    int i = blockIdx.x * 256 + threadIdx.x;
    int lane = threadIdx.x & 31, warp = threadIdx.x >> 5;
    int v = (i < NNODES) ? g_deg[i] : 0;
    int x = v;
    #pragma unroll
    for (int off = 1; off < 32; off <<= 1) {
        int y = __shfl_up_sync(~0u, x, off);
        if (lane >= off) x += y;
    }
    __shared__ int ws[8];
    if (lane == 31) ws[warp] = x;
    __syncthreads();
    if (threadIdx.x == 0) {
        int run = 0;
        #pragma unroll
        for (int w = 0; w < 8; w++) { int tmp = ws[w]; ws[w] = run; run += tmp; }
    }
    __syncthreads();
    int incl = x + ws[warp];
    int base = g_boff[blockIdx.x];
    if (i < NNODES) {
        int rs = base + incl - v;
        g_rowstart[i] = rs;
        g_cursor[i]   = rs;
        if (i == NNODES - 1) g_rowstart[NNODES] = base + incl;
    }
}

__global__ void scatter_kernel(const void* __restrict__ ei, int E) {
    int e = blockIdx.x * blockDim.x + threadIdx.x;
    if (e >= E) return;
    int s, d;
    if (g_idx64) {
        const long long* p = (const long long*)ei;
        s = (int)p[e]; d = (int)p[E + e];
    } else {
        const int* p = (const int*)ei;
        s = p[e]; d = p[E + e];
    }
    int pos = atomicAdd(&g_cursor[d], 1);
    g_csr_src[pos] = s;
}

// ---------------- tensor-core dual-weight GEMM -------------------------------
#define APAD 36
#define BPAD 68
__global__ __launch_bounds__(256) void gemm_tc(
        const float* __restrict__ A,
        const float* __restrict__ WL,
        const float* __restrict__ WR,
        float* __restrict__ C,
        int M, int NHALF, int NN) {
    __shared__ float As[128][APAD];
    __shared__ float Bs[32][BPAD];

    const int t = threadIdx.x;
    const int lane = t & 31, g = lane >> 2, tig = lane & 3;
    const int w = t >> 5, wr = w & 3, wc = w >> 2;
    const int rowBase = blockIdx.y << 7;
    const int colTile = blockIdx.x << 6;

    const float* W;
    int colBase;
    if (colTile >= NHALF) { W = WR; colBase = colTile - NHALF; }
    else                  { W = WL; colBase = colTile; }

    float acc[2][4][4];
    #pragma unroll
    for (int mi = 0; mi < 2; mi++)
        #pragma unroll
        for (int ni = 0; ni < 4; ni++)
            #pragma unroll
            for (int j = 0; j < 4; j++) acc[mi][ni][j] = 0.f;

    const int arow = t >> 3, ac4 = (t & 7) << 2;
    for (int k0 = 0; k0 < FIN; k0 += 32) {
        #pragma unroll
        for (int r = 0; r < 4; r++) {
            int row = arow + r * 32;
            int grow = rowBase + row;
            if (grow >= M) grow = M - 1;
            float4 v = *(const float4*)&A[(long)grow * FIN + k0 + ac4];
            *(float4*)&As[row][ac4] = v;
        }
        #pragma unroll
        for (int j = 0; j < 2; j++) {
            int i = t + j * 256;
            int brow = i >> 4, bc4 = (i & 15) << 2;
            float4 v = *(const float4*)&W[(long)(k0 + brow) * NHALF + colBase + bc4];
            *(float4*)&Bs[brow][bc4] = v;
        }
        __syncthreads();

        #pragma unroll
        for (int kk = 0; kk < 32; kk += 8) {
            unsigned ah[2][4], al[2][4], bh[4][2], bl[4][2];
            #pragma unroll
            for (int mi = 0; mi < 2; mi++) {
                int rb = wr * 32 + mi * 16;
                tfsplit(As[rb + g    ][kk + tig    ], ah[mi][0], al[mi][0]);
                tfsplit(As[rb + 8 + g][kk + tig    ], ah[mi][1], al[mi][1]);
                tfsplit(As[rb + g    ][kk + 4 + tig], ah[mi][2], al[mi][2]);
                tfsplit(As[rb + 8 + g][kk + 4 + tig], ah[mi][3], al[mi][3]);
            }
            #pragma unroll
            for (int ni = 0; ni < 4; ni++) {
                int col = wc * 32 + ni * 8 + g;
                tfsplit(Bs[kk + tig    ][col], bh[ni][0], bl[ni][0]);
                tfsplit(Bs[kk + 4 + tig][col], bh[ni][1], bl[ni][1]);
            }
            #pragma unroll
            for (int mi = 0; mi < 2; mi++)
                #pragma unroll
                for (int ni = 0; ni < 4; ni++) {
                    mma_tf32(acc[mi][ni], ah[mi], bh[ni]);
                    mma_tf32(acc[mi][ni], ah[mi], bl[ni]);
                    mma_tf32(acc[mi][ni], al[mi], bh[ni]);
                }
        }
        __syncthreads();
    }

    #pragma unroll
    for (int mi = 0; mi < 2; mi++) {
        int row0 = rowBase + wr * 32 + mi * 16 + g;
        #pragma unroll
        for (int ni = 0; ni < 4; ni++) {
            int col = colTile + wc * 32 + ni * 8 + 2 * tig;
            if (row0 < M)
                *(float2*)&C[(long)row0 * NN + col] =
                    make_float2(acc[mi][ni][0], acc[mi][ni][1]);
            if (row0 + 8 < M)
                *(float2*)&C[(long)(row0 + 8) * NN + col] =
                    make_float2(acc[mi][ni][2], acc[mi][ni][3]);
        }
    }
}

// ---------------- conv1: warp/node, software-pipelined gather ----------------
__global__ void conv1_kernel(const float* __restrict__ b1,
                             const float* __restrict__ att) {
    int w = (blockIdx.x * blockDim.x + threadIdx.x) >> 5;
    if (w >= NNODES) return;
    int lane = threadIdx.x & 31, c4 = lane << 2;

    float4 av = *(const float4*)&att[c4];
    float4 xr = *(const float4*)&g_xlr1[w * 256 + 128 + c4];
    float4 bb = *(const float4*)&b1[c4];

    float4 acc = make_float4(0.f, 0.f, 0.f, 0.f);
    float den = 0.f;

    int rs = g_rowstart[w], re = g_rowstart[w + 1];
    int cnt = re - rs + 1;                       // +1 self loop (iter 0)
    int sNxt = (cnt > 1) ? g_csr_src[rs] : 0;    // src for iter 1
    float4 aCur = *(const float4*)&g_xlr1[w * 256 + c4];   // self

    for (int i = 0; i < cnt; i++) {
        float4 a = aCur;
        if (i + 1 < cnt) {
            aCur = *(const float4*)&g_xlr1[(long)sNxt * 256 + c4];  // prefetch i+1
            if (i + 2 < cnt) sNxt = g_csr_src[rs + i + 1];          // prefetch i+2
        }
        float sc = lrelu(a.x + xr.x) * av.x + lrelu(a.y + xr.y) * av.y +
                   lrelu(a.z + xr.z) * av.z + lrelu(a.w + xr.w) * av.w;
        sc += __shfl_xor_sync(0xffffffffu, sc, 8);
        sc += __shfl_xor_sync(0xffffffffu, sc, 4);
        sc += __shfl_xor_sync(0xffffffffu, sc, 2);
        sc += __shfl_xor_sync(0xffffffffu, sc, 1);
        float p = expf(sc);
        acc.x += p * a.x; acc.y += p * a.y;
        acc.z += p * a.z; acc.w += p * a.w;
        den += p;
    }
    float inv = 1.f / den;
    float4 h;
    h.x = elu(acc.x * inv + bb.x);
    h.y = elu(acc.y * inv + bb.y);
    h.z = elu(acc.z * inv + bb.z);
    h.w = elu(acc.w * inv + bb.w);
    *(float4*)&g_h1[w * 128 + c4] = h;
}

// ---------------- conv2: 16 lanes/node, pipelined, + mean-pool ---------------
__global__ void conv2_kernel(const float* __restrict__ b2,
                             const float* __restrict__ att,
                             const void* __restrict__ batch) {
    int idx = blockIdx.x * blockDim.x + threadIdx.x;
    int n = idx >> 4;
    if (n >= NNODES) return;
    int l = threadIdx.x & 15, c4 = l << 2;
    unsigned gmask = 0xFFFFu << (threadIdx.x & 16);

    float4 av = *(const float4*)&att[c4];
    float4 xr = *(const float4*)&g_xlr2[n * 128 + 64 + c4];
    float4 bb = *(const float4*)&b2[c4];

    float4 acc = make_float4(0.f, 0.f, 0.f, 0.f);
    float den = 0.f;

    int rs = g_rowstart[n], re = g_rowstart[n + 1];
    int cnt = re - rs + 1;
    int sNxt = (cnt > 1) ? g_csr_src[rs] : 0;
    float4 aCur = *(const float4*)&g_xlr2[n * 128 + c4];

    for (int i = 0; i < cnt; i++) {
        float4 a = aCur;
        if (i + 1 < cnt) {
            aCur = *(const float4*)&g_xlr2[(long)sNxt * 128 + c4];
            if (i + 2 < cnt) sNxt = g_csr_src[rs + i + 1];
        }
        float sc = lrelu(a.x + xr.x) * av.x + lrelu(a.y + xr.y) * av.y +
                   lrelu(a.z + xr.z) * av.z + lrelu(a.w + xr.w) * av.w;
        sc += __shfl_xor_sync(gmask, sc, 8);
        sc += __shfl_xor_sync(gmask, sc, 4);
        sc += __shfl_xor_sync(gmask, sc, 2);
        sc += __shfl_xor_sync(gmask, sc, 1);
        float p = expf(sc);
        acc.x += p * a.x; acc.y += p * a.y;
        acc.z += p * a.z; acc.w += p * a.w;
        den += p;
    }
    float inv = 1.f / den;
    float4 h;
    h.x = elu(acc.x * inv + bb.x);
    h.y = elu(acc.y * inv + bb.y);
    h.z = elu(acc.z * inv + bb.z);
    h.w = elu(acc.w * inv + bb.w);

    int gph = g_idx64 ? (int)((const long long*)batch)[n]
                      : ((const int*)batch)[n];
    red_add4(&g_pool[gph * 64 + c4], h);
    if (l == 0) atomicAdd(&g_cnt[gph], 1.0f);
}

// ---------------- final: out = (pool/cnt) @ Wlin + blin ----------------------
__global__ void final_kernel(const float* __restrict__ Wlin,
                             const float* __restrict__ blin,
                             float* __restrict__ out) {
    int t = threadIdx.x;
    if (t >= NGRAPH * NCLS) return;
    int g = t / NCLS, j = t - g * NCLS;
    float inv = 1.f / fmaxf(g_cnt[g], 1.f);
    float s = 0.f;
    #pragma unroll
    for (int c = 0; c < 64; c++) s += g_pool[g * 64 + c] * Wlin[c * NCLS + j];
    out[t] = s * inv + blin[j];
}

// ---------------- launch ------------------------------------------------------
extern "C" void kernel_launch(void* const* d_in, const int* in_sizes, int n_in,
                              void* d_out, int out_size) {
    const float* x    = (const float*)d_in[0];
    const void*  ei   = d_in[1];
    const void*  bat  = d_in[2];
    const float* Wl1  = (const float*)d_in[3];
    const float* Wr1  = (const float*)d_in[4];
    const float* att1 = (const float*)d_in[5];
    const float* b1   = (const float*)d_in[6];
    const float* Wl2  = (const float*)d_in[7];
    const float* Wr2  = (const float*)d_in[8];
    const float* att2 = (const float*)d_in[9];
    const float* b2   = (const float*)d_in[10];
    const float* Wlin = (const float*)d_in[11];
    const float* blin = (const float*)d_in[12];
    float* out = (float*)d_out;

    int Nn = in_sizes[0] / 128;   // 50000
    int E  = in_sizes[1] / 2;     // 600000

    float *p_xlr1, *p_xlr2, *p_h1;
    cudaGetSymbolAddress((void**)&p_xlr1, g_xlr1);
    cudaGetSymbolAddress((void**)&p_xlr2, g_xlr2);
    cudaGetSymbolAddress((void**)&p_h1,   g_h1);

    // launch order: gemm1 at slot 4 (profiled slot), deps still satisfied
    detect_idx_kernel<<<1, 32>>>(ei);
    zero_kernel<<<(Nn + 255) / 256, 256>>>();
    hist_kernel<<<(E + 255) / 256, 256>>>(ei, E);

    dim3 g1(4, (Nn + 127) / 128);
    gemm_tc<<<g1, 256>>>(x, Wl1, Wr1, p_xlr1, Nn, 128, 256);   // slot 4

    scan1_kernel<<<NBLK, 256>>>();
    scan2_kernel<<<1, 256>>>();
    scan3_kernel<<<NBLK, 256>>>();
    scatter_kernel<<<(E + 255) / 256, 256>>>(ei, E);

    conv1_kernel<<<(Nn * 32 + 255) / 256, 256>>>(b1, att1);

    dim3 g2(2, (Nn + 127) / 128);
    gemm_tc<<<g2, 256>>>(p_h1, Wl2, Wr2, p_xlr2, Nn, 64, 128);
    conv2_kernel<<<(Nn * 16 + 255) / 256, 256>>>(b2, att2, bat);

    final_kernel<<<1, 640>>>(Wlin, blin, out);
}

// round 6
// speedup vs baseline: 1.4660x; 1.0667x over previous
#include <cuda_runtime.h>

#define NNODES 50000
#define NGRAPH 64
#define FIN    128
#define NCLS   10
#define MAXE   600000
#define NBLK   ((NNODES + 255) / 256)   // 196 scan blocks

// ---------------- scratch (static device arrays) -----------------------------
__device__ float g_xlr1[NNODES * 256];   // conv1: [xl(128) | xr(128)]
__device__ float g_h1  [NNODES * 128];   // conv1 output (post-ELU)
__device__ float g_xlr2[NNODES * 128];   // conv2: [xl(64) | xr(64)]
__device__ float g_pool[NGRAPH * 64];
__device__ float g_cnt [NGRAPH];
__device__ int   g_idx64;

__device__ int   g_deg     [NNODES];
__device__ int   g_rowstart[NNODES + 1];
__device__ int   g_cursor  [NNODES];
__device__ int   g_csr_src [MAXE];
__device__ int   g_bsum    [NBLK];
__device__ int   g_boff    [NBLK];

// ---------------- helpers -----------------------------------------------------
__device__ __forceinline__ void red_add4(float* p, float4 v) {
    asm volatile("red.global.add.v4.f32 [%0], {%1,%2,%3,%4};"
                 :: "l"(p), "f"(v.x), "f"(v.y), "f"(v.z), "f"(v.w) : "memory");
}
__device__ __forceinline__ float lrelu(float v) { return v > 0.f ? v : 0.2f * v; }
__device__ __forceinline__ float elu(float v)   { return v > 0.f ? v : expm1f(v); }

__device__ __forceinline__ unsigned f2tf(float f) {
    unsigned r;
    asm("cvt.rna.tf32.f32 %0, %1;" : "=r"(r) : "f"(f));
    return r;
}
__device__ __forceinline__ void tfsplit(float f, unsigned& hi, unsigned& lo) {
    hi = f2tf(f);
    lo = f2tf(f - __uint_as_float(hi));
}
__device__ __forceinline__ void mma_tf32(float* c, const unsigned* a, const unsigned* b) {
    asm volatile(
        "mma.sync.aligned.m16n8k8.row.col.f32.tf32.tf32.f32 "
        "{%0,%1,%2,%3}, {%4,%5,%6,%7}, {%8,%9}, {%0,%1,%2,%3};"
        : "+f"(c[0]), "+f"(c[1]), "+f"(c[2]), "+f"(c[3])
        : "r"(a[0]), "r"(a[1]), "r"(a[2]), "r"(a[3]), "r"(b[0]), "r"(b[1]));
}

// ---------------- dtype detection --------------------------------------------
__global__ void detect_idx_kernel(const void* ei) {
    if (threadIdx.x == 0) {
        const long long* p = (const long long*)ei;
        int ok = 1;
        for (int i = 0; i < 16; i++) {
            long long v = p[i];
            if (v < 0 || v >= NNODES) ok = 0;
        }
        g_idx64 = ok;
    }
}

// ---------------- zero small accumulators ------------------------------------
__global__ void zero_kernel() {
    int i = blockIdx.x * blockDim.x + threadIdx.x;
    if (i < NNODES)      g_deg[i] = 0;
    if (i < NGRAPH * 64) g_pool[i] = 0.f;
    if (i < NGRAPH)      g_cnt[i]  = 0.f;
}

// ---------------- CSR build ---------------------------------------------------
__global__ void hist_kernel(const void* __restrict__ ei, int E) {
    int e = blockIdx.x * blockDim.x + threadIdx.x;
    if (e >= E) return;
    int d = g_idx64 ? (int)((const long long*)ei)[E + e]
                    : ((const int*)ei)[E + e];
    atomicAdd(&g_deg[d], 1);
}

__global__ void scan1_kernel() {
    int i = blockIdx.x * 256 + threadIdx.x;
    int v = (i < NNODES) ? g_deg[i] : 0;
    int s = v;
    #pragma unroll
    for (int off = 16; off; off >>= 1) s += __shfl_xor_sync(~0u, s, off);
    __shared__ int ws[8];
    if ((threadIdx.x & 31) == 0) ws[threadIdx.x >> 5] = s;
    __syncthreads();
    if (threadIdx.x == 0) {
        int t = 0;
        #pragma unroll
        for (int w = 0; w < 8; w++) t += ws[w];
        g_bsum[blockIdx.x] = t;
    }
}

__global__ void scan2_kernel() {
    __shared__ int sh[256];
    int t = threadIdx.x;
    int v = (t < NBLK) ? g_bsum[t] : 0;
    sh[t] = v;
    __syncthreads();
    for (int off = 1; off < 256; off <<= 1) {
        int u = (t >= off) ? sh[t - off] : 0;
        __syncthreads();
        sh[t] += u;
        __syncthreads();
    }
    if (t < NBLK) g_boff[t] = sh[t] - v;
}

__global__ void scan3_kernel() {
    int i = blockIdx.x * 256 + threadIdx.x;
    int lane = threadIdx.x & 31, warp = threadIdx.x >> 5;
    int v = (i < NNODES) ? g_deg[i] : 0;
    int x = v;
    #pragma unroll
    for (int off = 1; off < 32; off <<= 1) {
        int y = __shfl_up_sync(~0u, x, off);
        if (lane >= off) x += y;
    }
    __shared__ int ws[8];
    if (lane == 31) ws[warp] = x;
    __syncthreads();
    if (threadIdx.x == 0) {
        int run = 0;
        #pragma unroll
        for (int w = 0; w < 8; w++) { int tmp = ws[w]; ws[w] = run; run += tmp; }
    }
    __syncthreads();
    int incl = x + ws[warp];
    int base = g_boff[blockIdx.x];
    if (i < NNODES) {
        int rs = base + incl - v;
        g_rowstart[i] = rs;
        g_cursor[i]   = rs;
        if (i == NNODES - 1) g_rowstart[NNODES] = base + incl;
    }
}

__global__ void scatter_kernel(const void* __restrict__ ei, int E) {
    int e = blockIdx.x * blockDim.x + threadIdx.x;
    if (e >= E) return;
    int s, d;
    if (g_idx64) {
        const long long* p = (const long long*)ei;
        s = (int)p[e]; d = (int)p[E + e];
    } else {
        const int* p = (const int*)ei;
        s = p[e]; d = p[E + e];
    }
    int pos = atomicAdd(&g_cursor[d], 1);
    g_csr_src[pos] = s;
}

// ---------------- tensor-core dual-weight GEMM (pre-split tf32) --------------
// BM=64, BN=64, 8 warps each 16x32. hi/lo split done ONCE at smem store.
#define APAD 36
#define BPAD 72
__global__ __launch_bounds__(256) void gemm_tc(
        const float* __restrict__ A,
        const float* __restrict__ WL,
        const float* __restrict__ WR,
        float* __restrict__ C,
        int M, int NHALF, int NN) {
    __shared__ unsigned AsH[64][APAD], AsL[64][APAD];
    __shared__ unsigned BsH[32][BPAD], BsL[32][BPAD];

    const int t = threadIdx.x;
    const int lane = t & 31, g = lane >> 2, tig = lane & 3;
    const int w = t >> 5, wr = w & 3, wc = w >> 2;   // warp tile 16x32
    const int rowBase = blockIdx.y << 6;
    const int colTile = blockIdx.x << 6;

    const float* W;
    int colBase;
    if (colTile >= NHALF) { W = WR; colBase = colTile - NHALF; }
    else                  { W = WL; colBase = colTile; }

    float acc[4][4];
    #pragma unroll
    for (int ni = 0; ni < 4; ni++)
        #pragma unroll
        for (int j = 0; j < 4; j++) acc[ni][j] = 0.f;

    const int arow = t >> 3, ac4 = (t & 7) << 2;   // 32 rows x 8 float4
    for (int k0 = 0; k0 < FIN; k0 += 32) {
        #pragma unroll
        for (int r = 0; r < 2; r++) {
            int row = arow + r * 32;
            int grow = rowBase + row;
            if (grow >= M) grow = M - 1;
            float4 v = *(const float4*)&A[(long)grow * FIN + k0 + ac4];
            uint4 h, l;
            tfsplit(v.x, h.x, l.x); tfsplit(v.y, h.y, l.y);
            tfsplit(v.z, h.z, l.z); tfsplit(v.w, h.w, l.w);
            *(uint4*)&AsH[row][ac4] = h;
            *(uint4*)&AsL[row][ac4] = l;
        }
        #pragma unroll
        for (int j = 0; j < 2; j++) {
            int i = t + j * 256;
            int brow = i >> 4, bc4 = (i & 15) << 2;
            float4 v = *(const float4*)&W[(long)(k0 + brow) * NHALF + colBase + bc4];
            uint4 h, l;
            tfsplit(v.x, h.x, l.x); tfsplit(v.y, h.y, l.y);
            tfsplit(v.z, h.z, l.z); tfsplit(v.w, h.w, l.w);
            *(uint4*)&BsH[brow][bc4] = h;
            *(uint4*)&BsL[brow][bc4] = l;
        }
        __syncthreads();

        #pragma unroll
        for (int kk = 0; kk < 32; kk += 8) {
            unsigned ah[4], al[4], bh[4][2], bl[4][2];
            int ra = wr * 16 + g;
            ah[0] = AsH[ra    ][kk + tig];     al[0] = AsL[ra    ][kk + tig];
            ah[1] = AsH[ra + 8][kk + tig];     al[1] = AsL[ra + 8][kk + tig];
            ah[2] = AsH[ra    ][kk + 4 + tig]; al[2] = AsL[ra    ][kk + 4 + tig];
            ah[3] = AsH[ra + 8][kk + 4 + tig]; al[3] = AsL[ra + 8][kk + 4 + tig];
            #pragma unroll
            for (int ni = 0; ni < 4; ni++) {
                int col = wc * 32 + ni * 8 + g;
                bh[ni][0] = BsH[kk + tig    ][col];
                bh[ni][1] = BsH[kk + 4 + tig][col];
                bl[ni][0] = BsL[kk + tig    ][col];
                bl[ni][1] = BsL[kk + 4 + tig][col];
            }
            #pragma unroll
            for (int ni = 0; ni < 4; ni++) {
                mma_tf32(acc[ni], ah, bh[ni]);
                mma_tf32(acc[ni], ah, bl[ni]);
                mma_tf32(acc[ni], al, bh[ni]);
            }
        }
        __syncthreads();
    }

    int row0 = rowBase + wr * 16 + g;
    #pragma unroll
    for (int ni = 0; ni < 4; ni++) {
        int col = colTile + wc * 32 + ni * 8 + 2 * tig;
        if (row0 < M)
            *(float2*)&C[(long)row0 * NN + col] =
                make_float2(acc[ni][0], acc[ni][1]);
        if (row0 + 8 < M)
            *(float2*)&C[(long)(row0 + 8) * NN + col] =
                make_float2(acc[ni][2], acc[ni][3]);
    }
}

// ---------------- conv1: warp/node, unroll-2 dual score chains ---------------
__global__ void conv1_kernel(const float* __restrict__ b1,
                             const float* __restrict__ att) {
    int w = (blockIdx.x * blockDim.x + threadIdx.x) >> 5;
    if (w >= NNODES) return;
    int lane = threadIdx.x & 31, c4 = lane << 2;

    float4 av = *(const float4*)&att[c4];
    float4 xr = *(const float4*)&g_xlr1[w * 256 + 128 + c4];
    float4 bb = *(const float4*)&b1[c4];

    float4 acc = make_float4(0.f, 0.f, 0.f, 0.f);
    float den = 0.f;

    int rs = g_rowstart[w], re = g_rowstart[w + 1];
    int cnt = re - rs + 1;                        // virtual edge 0 = self loop

    for (int i = 0; i < cnt; i += 2) {
        int sA = (i == 0) ? w : g_csr_src[rs + i - 1];
        bool hasB = (i + 1 < cnt);
        int sB = hasB ? g_csr_src[rs + i] : sA;
        float4 aA = *(const float4*)&g_xlr1[(long)sA * 256 + c4];
        float4 aB = *(const float4*)&g_xlr1[(long)sB * 256 + c4];

        float eA = lrelu(aA.x + xr.x) * av.x + lrelu(aA.y + xr.y) * av.y +
                   lrelu(aA.z + xr.z) * av.z + lrelu(aA.w + xr.w) * av.w;
        float eB = lrelu(aB.x + xr.x) * av.x + lrelu(aB.y + xr.y) * av.y +
                   lrelu(aB.z + xr.z) * av.z + lrelu(aB.w + xr.w) * av.w;
        #pragma unroll
        for (int off = 8; off; off >>= 1) {
            eA += __shfl_xor_sync(0xffffffffu, eA, off);
            eB += __shfl_xor_sync(0xffffffffu, eB, off);
        }
        float pA = __expf(eA);
        float pB = hasB ? __expf(eB) : 0.f;
        acc.x += pA * aA.x + pB * aB.x;
        acc.y += pA * aA.y + pB * aB.y;
        acc.z += pA * aA.z + pB * aB.z;
        acc.w += pA * aA.w + pB * aB.w;
        den += pA + pB;
    }
    float inv = 1.f / den;
    float4 h;
    h.x = elu(acc.x * inv + bb.x);
    h.y = elu(acc.y * inv + bb.y);
    h.z = elu(acc.z * inv + bb.z);
    h.w = elu(acc.w * inv + bb.w);
    *(float4*)&g_h1[w * 128 + c4] = h;
}

// ---------------- conv2: 16 lanes/node, unroll-2, + mean-pool ----------------
__global__ void conv2_kernel(const float* __restrict__ b2,
                             const float* __restrict__ att,
                             const void* __restrict__ batch) {
    int idx = blockIdx.x * blockDim.x + threadIdx.x;
    int n = idx >> 4;
    if (n >= NNODES) return;
    int l = threadIdx.x & 15, c4 = l << 2;
    unsigned gmask = 0xFFFFu << (threadIdx.x & 16);

    float4 av = *(const float4*)&att[c4];
    float4 xr = *(const float4*)&g_xlr2[n * 128 + 64 + c4];
    float4 bb = *(const float4*)&b2[c4];

    float4 acc = make_float4(0.f, 0.f, 0.f, 0.f);
    float den = 0.f;

    int rs = g_rowstart[n], re = g_rowstart[n + 1];
    int cnt = re - rs + 1;

    for (int i = 0; i < cnt; i += 2) {
        int sA = (i == 0) ? n : g_csr_src[rs + i - 1];
        bool hasB = (i + 1 < cnt);
        int sB = hasB ? g_csr_src[rs + i] : sA;
        float4 aA = *(const float4*)&g_xlr2[(long)sA * 128 + c4];
        float4 aB = *(const float4*)&g_xlr2[(long)sB * 128 + c4];

        float eA = lrelu(aA.x + xr.x) * av.x + lrelu(aA.y + xr.y) * av.y +
                   lrelu(aA.z + xr.z) * av.z + lrelu(aA.w + xr.w) * av.w;
        float eB = lrelu(aB.x + xr.x) * av.x + lrelu(aB.y + xr.y) * av.y +
                   lrelu(aB.z + xr.z) * av.z + lrelu(aB.w + xr.w) * av.w;
        #pragma unroll
        for (int off = 8; off; off >>= 1) {
            eA += __shfl_xor_sync(gmask, eA, off);
            eB += __shfl_xor_sync(gmask, eB, off);
        }
        float pA = __expf(eA);
        float pB = hasB ? __expf(eB) : 0.f;
        acc.x += pA * aA.x + pB * aB.x;
        acc.y += pA * aA.y + pB * aB.y;
        acc.z += pA * aA.z + pB * aB.z;
        acc.w += pA * aA.w + pB * aB.w;
        den += pA + pB;
    }
    float inv = 1.f / den;
    float4 h;
    h.x = elu(acc.x * inv + bb.x);
    h.y = elu(acc.y * inv + bb.y);
    h.z = elu(acc.z * inv + bb.z);
    h.w = elu(acc.w * inv + bb.w);

    int gph = g_idx64 ? (int)((const long long*)batch)[n]
                      : ((const int*)batch)[n];
    red_add4(&g_pool[gph * 64 + c4], h);
    if (l == 0) atomicAdd(&g_cnt[gph], 1.0f);
}

// ---------------- final: out = (pool/cnt) @ Wlin + blin ----------------------
__global__ void final_kernel(const float* __restrict__ Wlin,
                             const float* __restrict__ blin,
                             float* __restrict__ out) {
    int t = threadIdx.x;
    if (t >= NGRAPH * NCLS) return;
    int g = t / NCLS, j = t - g * NCLS;
    float inv = 1.f / fmaxf(g_cnt[g], 1.f);
    float s = 0.f;
    #pragma unroll
    for (int c = 0; c < 64; c++) s += g_pool[g * 64 + c] * Wlin[c * NCLS + j];
    out[t] = s * inv + blin[j];
}

// ---------------- launch ------------------------------------------------------
extern "C" void kernel_launch(void* const* d_in, const int* in_sizes, int n_in,
                              void* d_out, int out_size) {
    const float* x    = (const float*)d_in[0];
    const void*  ei   = d_in[1];
    const void*  bat  = d_in[2];
    const float* Wl1  = (const float*)d_in[3];
    const float* Wr1  = (const float*)d_in[4];
    const float* att1 = (const float*)d_in[5];
    const float* b1   = (const float*)d_in[6];
    const float* Wl2  = (const float*)d_in[7];
    const float* Wr2  = (const float*)d_in[8];
    const float* att2 = (const float*)d_in[9];
    const float* b2   = (const float*)d_in[10];
    const float* Wlin = (const float*)d_in[11];
    const float* blin = (const float*)d_in[12];
    float* out = (float*)d_out;

    int Nn = in_sizes[0] / 128;   // 50000
    int E  = in_sizes[1] / 2;     // 600000

    float *p_xlr1, *p_xlr2, *p_h1;
    cudaGetSymbolAddress((void**)&p_xlr1, g_xlr1);
    cudaGetSymbolAddress((void**)&p_xlr2, g_xlr2);
    cudaGetSymbolAddress((void**)&p_h1,   g_h1);

    detect_idx_kernel<<<1, 32>>>(ei);
    zero_kernel<<<(Nn + 255) / 256, 256>>>();
    hist_kernel<<<(E + 255) / 256, 256>>>(ei, E);

    dim3 g1(4, (Nn + 63) / 64);
    gemm_tc<<<g1, 256>>>(x, Wl1, Wr1, p_xlr1, Nn, 128, 256);   // profiled slot

    scan1_kernel<<<NBLK, 256>>>();
    scan2_kernel<<<1, 256>>>();
    scan3_kernel<<<NBLK, 256>>>();
    scatter_kernel<<<(E + 255) / 256, 256>>>(ei, E);

    conv1_kernel<<<(Nn * 32 + 255) / 256, 256>>>(b1, att1);

    dim3 g2(2, (Nn + 63) / 64);
    gemm_tc<<<g2, 256>>>(p_h1, Wl2, Wr2, p_xlr2, Nn, 64, 128);
    conv2_kernel<<<(Nn * 16 + 255) / 256, 256>>>(b2, att2, bat);

    final_kernel<<<1, 640>>>(Wlin, blin, out);
}

// round 7
// speedup vs baseline: 1.5028x; 1.0251x over previous
#include <cuda_runtime.h>

#define NNODES 50000
#define NGRAPH 64
#define FIN    128
#define NCLS   10
#define MAXE   600000
#define NBLK   ((NNODES + 255) / 256)   // 196 scan blocks

#define APAD 36
#define BPAD 72
#define GEMM_SMEM ((2 * 128 * APAD + 2 * 32 * BPAD) * 4)   // 55296 bytes

// ---------------- scratch (static device arrays) -----------------------------
__device__ float g_xlr1[NNODES * 256];   // conv1: [xl(128) | xr(128)]
__device__ float g_h1  [NNODES * 128];   // conv1 output (post-ELU)
__device__ float g_xlr2[NNODES * 128];   // conv2: [xl(64) | xr(64)]
__device__ float g_pool[NGRAPH * 64];
__device__ float g_cnt [NGRAPH];
__device__ int   g_idx64;

__device__ int   g_deg     [NNODES];
__device__ int   g_rowstart[NNODES + 1];
__device__ int   g_cursor  [NNODES];
__device__ int   g_csr_src [MAXE];
__device__ int   g_bsum    [NBLK];
__device__ int   g_boff    [NBLK];

// ---------------- helpers -----------------------------------------------------
__device__ __forceinline__ void red_add4(float* p, float4 v) {
    asm volatile("red.global.add.v4.f32 [%0], {%1,%2,%3,%4};"
                 :: "l"(p), "f"(v.x), "f"(v.y), "f"(v.z), "f"(v.w) : "memory");
}
__device__ __forceinline__ float lrelu(float v) { return v > 0.f ? v : 0.2f * v; }
__device__ __forceinline__ float elu(float v)   { return v > 0.f ? v : expm1f(v); }

__device__ __forceinline__ unsigned f2tf(float f) {
    unsigned r;
    asm("cvt.rna.tf32.f32 %0, %1;" : "=r"(r) : "f"(f));
    return r;
}
__device__ __forceinline__ void tfsplit(float f, unsigned& hi, unsigned& lo) {
    hi = f2tf(f);
    lo = f2tf(f - __uint_as_float(hi));
}
__device__ __forceinline__ void mma_tf32(float* c, const unsigned* a, const unsigned* b) {
    asm volatile(
        "mma.sync.aligned.m16n8k8.row.col.f32.tf32.tf32.f32 "
        "{%0,%1,%2,%3}, {%4,%5,%6,%7}, {%8,%9}, {%0,%1,%2,%3};"
        : "+f"(c[0]), "+f"(c[1]), "+f"(c[2]), "+f"(c[3])
        : "r"(a[0]), "r"(a[1]), "r"(a[2]), "r"(a[3]), "r"(b[0]), "r"(b[1]));
}

// ---------------- dtype detection --------------------------------------------
__global__ void detect_idx_kernel(const void* ei) {
    if (threadIdx.x == 0) {
        const long long* p = (const long long*)ei;
        int ok = 1;
        for (int i = 0; i < 16; i++) {
            long long v = p[i];
            if (v < 0 || v >= NNODES) ok = 0;
        }
        g_idx64 = ok;
    }
}

// ---------------- zero small accumulators ------------------------------------
__global__ void zero_kernel() {
    int i = blockIdx.x * blockDim.x + threadIdx.x;
    if (i < NNODES)      g_deg[i] = 0;
    if (i < NGRAPH * 64) g_pool[i] = 0.f;
    if (i < NGRAPH)      g_cnt[i]  = 0.f;
}

// ---------------- CSR build ---------------------------------------------------
__global__ void hist_kernel(const void* __restrict__ ei, int E) {
    int e = blockIdx.x * blockDim.x + threadIdx.x;
    if (e >= E) return;
    int d = g_idx64 ? (int)((const long long*)ei)[E + e]
                    : ((const int*)ei)[E + e];
    atomicAdd(&g_deg[d], 1);
}

__global__ void scan1_kernel() {
    int i = blockIdx.x * 256 + threadIdx.x;
    int v = (i < NNODES) ? g_deg[i] : 0;
    int s = v;
    #pragma unroll
    for (int off = 16; off; off >>= 1) s += __shfl_xor_sync(~0u, s, off);
    __shared__ int ws[8];
    if ((threadIdx.x & 31) == 0) ws[threadIdx.x >> 5] = s;
    __syncthreads();
    if (threadIdx.x == 0) {
        int t = 0;
        #pragma unroll
        for (int w = 0; w < 8; w++) t += ws[w];
        g_bsum[blockIdx.x] = t;
    }
}

__global__ void scan2_kernel() {
    __shared__ int sh[256];
    int t = threadIdx.x;
    int v = (t < NBLK) ? g_bsum[t] : 0;
    sh[t] = v;
    __syncthreads();
    for (int off = 1; off < 256; off <<= 1) {
        int u = (t >= off) ? sh[t - off] : 0;
        __syncthreads();
        sh[t] += u;
        __syncthreads();
    }
    if (t < NBLK) g_boff[t] = sh[t] - v;
}

__global__ void scan3_kernel() {
    int i = blockIdx.x * 256 + threadIdx.x;
    int lane = threadIdx.x & 31, warp = threadIdx.x >> 5;
    int v = (i < NNODES) ? g_deg[i] : 0;
    int x = v;
    #pragma unroll
    for (int off = 1; off < 32; off <<= 1) {
        int y = __shfl_up_sync(~0u, x, off);
        if (lane >= off) x += y;
    }
    __shared__ int ws[8];
    if (lane == 31) ws[warp] = x;
    __syncthreads();
    if (threadIdx.x == 0) {
        int run = 0;
        #pragma unroll
        for (int w = 0; w < 8; w++) { int tmp = ws[w]; ws[w] = run; run += tmp; }
    }
    __syncthreads();
    int incl = x + ws[warp];
    int base = g_boff[blockIdx.x];
    if (i < NNODES) {
        int rs = base + incl - v;
        g_rowstart[i] = rs;
        g_cursor[i]   = rs;
        if (i == NNODES - 1) g_rowstart[NNODES] = base + incl;
    }
}

__global__ void scatter_kernel(const void* __restrict__ ei, int E) {
    int e = blockIdx.x * blockDim.x + threadIdx.x;
    if (e >= E) return;
    int s, d;
    if (g_idx64) {
        const long long* p = (const long long*)ei;
        s = (int)p[e]; d = (int)p[E + e];
    } else {
        const int* p = (const int*)ei;
        s = p[e]; d = p[E + e];
    }
    int pos = atomicAdd(&g_cursor[d], 1);
    g_csr_src[pos] = s;
}

// ---------------- tensor-core dual-weight GEMM (v3) --------------------------
// BM=128, BN=64, 8 warps each 32x32. Pre-split hi/lo in dynamic smem (55 KB).
__global__ __launch_bounds__(256) void gemm_tc(
        const float* __restrict__ A,
        const float* __restrict__ WL,
        const float* __restrict__ WR,
        float* __restrict__ C,
        int M, int NHALF, int NN) {
    extern __shared__ unsigned sm[];
    unsigned* AsH = sm;                       // 128 * APAD
    unsigned* AsL = AsH + 128 * APAD;
    unsigned* BsH = AsL + 128 * APAD;         // 32 * BPAD
    unsigned* BsL = BsH + 32 * BPAD;

    const int t = threadIdx.x;
    const int lane = t & 31, g = lane >> 2, tig = lane & 3;
    const int w = t >> 5, wr = w & 3, wc = w >> 2;   // warp tile 32x32
    const int rowBase = blockIdx.y << 7;
    const int colTile = blockIdx.x << 6;

    const float* W;
    int colBase;
    if (colTile >= NHALF) { W = WR; colBase = colTile - NHALF; }
    else                  { W = WL; colBase = colTile; }

    float acc[2][4][4];
    #pragma unroll
    for (int mi = 0; mi < 2; mi++)
        #pragma unroll
        for (int ni = 0; ni < 4; ni++)
            #pragma unroll
            for (int j = 0; j < 4; j++) acc[mi][ni][j] = 0.f;

    const int arow = t >> 3, ac4 = (t & 7) << 2;   // 32 rows/iter x 8 float4
    for (int k0 = 0; k0 < FIN; k0 += 32) {
        #pragma unroll
        for (int r = 0; r < 4; r++) {
            int row = arow + r * 32;
            int grow = rowBase + row;
            if (grow >= M) grow = M - 1;
            float4 v = *(const float4*)&A[(long)grow * FIN + k0 + ac4];
            uint4 h, l;
            tfsplit(v.x, h.x, l.x); tfsplit(v.y, h.y, l.y);
            tfsplit(v.z, h.z, l.z); tfsplit(v.w, h.w, l.w);
            *(uint4*)&AsH[row * APAD + ac4] = h;
            *(uint4*)&AsL[row * APAD + ac4] = l;
        }
        #pragma unroll
        for (int j = 0; j < 2; j++) {
            int i = t + j * 256;
            int brow = i >> 4, bc4 = (i & 15) << 2;
            float4 v = *(const float4*)&W[(long)(k0 + brow) * NHALF + colBase + bc4];
            uint4 h, l;
            tfsplit(v.x, h.x, l.x); tfsplit(v.y, h.y, l.y);
            tfsplit(v.z, h.z, l.z); tfsplit(v.w, h.w, l.w);
            *(uint4*)&BsH[brow * BPAD + bc4] = h;
            *(uint4*)&BsL[brow * BPAD + bc4] = l;
        }
        __syncthreads();

        #pragma unroll
        for (int kk = 0; kk < 32; kk += 8) {
            unsigned ah[2][4], al[2][4], bh[4][2], bl[4][2];
            #pragma unroll
            for (int mi = 0; mi < 2; mi++) {
                int rb = (wr * 32 + mi * 16 + g) * APAD;
                ah[mi][0] = AsH[rb + kk + tig];
                ah[mi][1] = AsH[rb + 8 * APAD + kk + tig];
                ah[mi][2] = AsH[rb + kk + 4 + tig];
                ah[mi][3] = AsH[rb + 8 * APAD + kk + 4 + tig];
                al[mi][0] = AsL[rb + kk + tig];
                al[mi][1] = AsL[rb + 8 * APAD + kk + tig];
                al[mi][2] = AsL[rb + kk + 4 + tig];
                al[mi][3] = AsL[rb + 8 * APAD + kk + 4 + tig];
            }
            #pragma unroll
            for (int ni = 0; ni < 4; ni++) {
                int col = wc * 32 + ni * 8 + g;
                bh[ni][0] = BsH[(kk + tig) * BPAD + col];
                bh[ni][1] = BsH[(kk + 4 + tig) * BPAD + col];
                bl[ni][0] = BsL[(kk + tig) * BPAD + col];
                bl[ni][1] = BsL[(kk + 4 + tig) * BPAD + col];
            }
            #pragma unroll
            for (int mi = 0; mi < 2; mi++)
                #pragma unroll
                for (int ni = 0; ni < 4; ni++) {
                    mma_tf32(acc[mi][ni], ah[mi], bh[ni]);
                    mma_tf32(acc[mi][ni], ah[mi], bl[ni]);
                    mma_tf32(acc[mi][ni], al[mi], bh[ni]);
                }
        }
        __syncthreads();
    }

    #pragma unroll
    for (int mi = 0; mi < 2; mi++) {
        int row0 = rowBase + wr * 32 + mi * 16 + g;
        #pragma unroll
        for (int ni = 0; ni < 4; ni++) {
            int col = colTile + wc * 32 + ni * 8 + 2 * tig;
            if (row0 < M)
                *(float2*)&C[(long)row0 * NN + col] =
                    make_float2(acc[mi][ni][0], acc[mi][ni][1]);
            if (row0 + 8 < M)
                *(float2*)&C[(long)(row0 + 8) * NN + col] =
                    make_float2(acc[mi][ni][2], acc[mi][ni][3]);
        }
    }
}

// ---------------- conv1: warp/node, unroll-2 dual score chains ---------------
__global__ void conv1_kernel(const float* __restrict__ b1,
                             const float* __restrict__ att) {
    int w = (blockIdx.x * blockDim.x + threadIdx.x) >> 5;
    if (w >= NNODES) return;
    int lane = threadIdx.x & 31, c4 = lane << 2;

    float4 av = *(const float4*)&att[c4];
    float4 xr = *(const float4*)&g_xlr1[w * 256 + 128 + c4];
    float4 bb = *(const float4*)&b1[c4];

    float4 acc = make_float4(0.f, 0.f, 0.f, 0.f);
    float den = 0.f;

    int rs = g_rowstart[w], re = g_rowstart[w + 1];
    int cnt = re - rs + 1;                        // virtual edge 0 = self loop

    for (int i = 0; i < cnt; i += 2) {
        int sA = (i == 0) ? w : g_csr_src[rs + i - 1];
        bool hasB = (i + 1 < cnt);
        int sB = hasB ? g_csr_src[rs + i] : sA;
        float4 aA = *(const float4*)&g_xlr1[(long)sA * 256 + c4];
        float4 aB = *(const float4*)&g_xlr1[(long)sB * 256 + c4];

        float eA = lrelu(aA.x + xr.x) * av.x + lrelu(aA.y + xr.y) * av.y +
                   lrelu(aA.z + xr.z) * av.z + lrelu(aA.w + xr.w) * av.w;
        float eB = lrelu(aB.x + xr.x) * av.x + lrelu(aB.y + xr.y) * av.y +
                   lrelu(aB.z + xr.z) * av.z + lrelu(aB.w + xr.w) * av.w;
        #pragma unroll
        for (int off = 8; off; off >>= 1) {
            eA += __shfl_xor_sync(0xffffffffu, eA, off);
            eB += __shfl_xor_sync(0xffffffffu, eB, off);
        }
        float pA = __expf(eA);
        float pB = hasB ? __expf(eB) : 0.f;
        acc.x += pA * aA.x + pB * aB.x;
        acc.y += pA * aA.y + pB * aB.y;
        acc.z += pA * aA.z + pB * aB.z;
        acc.w += pA * aA.w + pB * aB.w;
        den += pA + pB;
    }
    float inv = 1.f / den;
    float4 h;
    h.x = elu(acc.x * inv + bb.x);
    h.y = elu(acc.y * inv + bb.y);
    h.z = elu(acc.z * inv + bb.z);
    h.w = elu(acc.w * inv + bb.w);
    *(float4*)&g_h1[w * 128 + c4] = h;
}

// ---------------- conv2: 16 lanes/node, unroll-2, + mean-pool ----------------
__global__ void conv2_kernel(const float* __restrict__ b2,
                             const float* __restrict__ att,
                             const void* __restrict__ batch) {
    int idx = blockIdx.x * blockDim.x + threadIdx.x;
    int n = idx >> 4;
    if (n >= NNODES) return;
    int l = threadIdx.x & 15, c4 = l << 2;
    unsigned gmask = 0xFFFFu << (threadIdx.x & 16);

    float4 av = *(const float4*)&att[c4];
    float4 xr = *(const float4*)&g_xlr2[n * 128 + 64 + c4];
    float4 bb = *(const float4*)&b2[c4];

    float4 acc = make_float4(0.f, 0.f, 0.f, 0.f);
    float den = 0.f;

    int rs = g_rowstart[n], re = g_rowstart[n + 1];
    int cnt = re - rs + 1;

    for (int i = 0; i < cnt; i += 2) {
        int sA = (i == 0) ? n : g_csr_src[rs + i - 1];
        bool hasB = (i + 1 < cnt);
        int sB = hasB ? g_csr_src[rs + i] : sA;
        float4 aA = *(const float4*)&g_xlr2[(long)sA * 128 + c4];
        float4 aB = *(const float4*)&g_xlr2[(long)sB * 128 + c4];

        float eA = lrelu(aA.x + xr.x) * av.x + lrelu(aA.y + xr.y) * av.y +
                   lrelu(aA.z + xr.z) * av.z + lrelu(aA.w + xr.w) * av.w;
        float eB = lrelu(aB.x + xr.x) * av.x + lrelu(aB.y + xr.y) * av.y +
                   lrelu(aB.z + xr.z) * av.z + lrelu(aB.w + xr.w) * av.w;
        #pragma unroll
        for (int off = 8; off; off >>= 1) {
            eA += __shfl_xor_sync(gmask, eA, off);
            eB += __shfl_xor_sync(gmask, eB, off);
        }
        float pA = __expf(eA);
        float pB = hasB ? __expf(eB) : 0.f;
        acc.x += pA * aA.x + pB * aB.x;
        acc.y += pA * aA.y + pB * aB.y;
        acc.z += pA * aA.z + pB * aB.z;
        acc.w += pA * aA.w + pB * aB.w;
        den += pA + pB;
    }
    float inv = 1.f / den;
    float4 h;
    h.x = elu(acc.x * inv + bb.x);
    h.y = elu(acc.y * inv + bb.y);
    h.z = elu(acc.z * inv + bb.z);
    h.w = elu(acc.w * inv + bb.w);

    int gph = g_idx64 ? (int)((const long long*)batch)[n]
                      : ((const int*)batch)[n];
    red_add4(&g_pool[gph * 64 + c4], h);
    if (l == 0) atomicAdd(&g_cnt[gph], 1.0f);
}

// ---------------- final: out = (pool/cnt) @ Wlin + blin ----------------------
__global__ void final_kernel(const float* __restrict__ Wlin,
                             const float* __restrict__ blin,
                             float* __restrict__ out) {
    int t = threadIdx.x;
    if (t >= NGRAPH * NCLS) return;
    int g = t / NCLS, j = t - g * NCLS;
    float inv = 1.f / fmaxf(g_cnt[g], 1.f);
    float s = 0.f;
    #pragma unroll
    for (int c = 0; c < 64; c++) s += g_pool[g * 64 + c] * Wlin[c * NCLS + j];
    out[t] = s * inv + blin[j];
}

// ---------------- launch ------------------------------------------------------
extern "C" void kernel_launch(void* const* d_in, const int* in_sizes, int n_in,
                              void* d_out, int out_size) {
    const float* x    = (const float*)d_in[0];
    const void*  ei   = d_in[1];
    const void*  bat  = d_in[2];
    const float* Wl1  = (const float*)d_in[3];
    const float* Wr1  = (const float*)d_in[4];
    const float* att1 = (const float*)d_in[5];
    const float* b1   = (const float*)d_in[6];
    const float* Wl2  = (const float*)d_in[7];
    const float* Wr2  = (const float*)d_in[8];
    const float* att2 = (const float*)d_in[9];
    const float* b2   = (const float*)d_in[10];
    const float* Wlin = (const float*)d_in[11];
    const float* blin = (const float*)d_in[12];
    float* out = (float*)d_out;

    int Nn = in_sizes[0] / 128;   // 50000
    int E  = in_sizes[1] / 2;     // 600000

    float *p_xlr1, *p_xlr2, *p_h1;
    cudaGetSymbolAddress((void**)&p_xlr1, g_xlr1);
    cudaGetSymbolAddress((void**)&p_xlr2, g_xlr2);
    cudaGetSymbolAddress((void**)&p_h1,   g_h1);

    cudaFuncSetAttribute(gemm_tc,
        cudaFuncAttributeMaxDynamicSharedMemorySize, GEMM_SMEM);

    detect_idx_kernel<<<1, 32>>>(ei);
    zero_kernel<<<(Nn + 255) / 256, 256>>>();
    hist_kernel<<<(E + 255) / 256, 256>>>(ei, E);

    dim3 g1(4, (Nn + 127) / 128);
    gemm_tc<<<g1, 256, GEMM_SMEM>>>(x, Wl1, Wr1, p_xlr1, Nn, 128, 256);  // profiled slot

    scan1_kernel<<<NBLK, 256>>>();
    scan2_kernel<<<1, 256>>>();
    scan3_kernel<<<NBLK, 256>>>();
    scatter_kernel<<<(E + 255) / 256, 256>>>(ei, E);

    conv1_kernel<<<(Nn * 32 + 255) / 256, 256>>>(b1, att1);

    dim3 g2(2, (Nn + 127) / 128);
    gemm_tc<<<g2, 256, GEMM_SMEM>>>(p_h1, Wl2, Wr2, p_xlr2, Nn, 64, 128);
    conv2_kernel<<<(Nn * 16 + 255) / 256, 256>>>(b2, att2, bat);

    final_kernel<<<1, 640>>>(Wlin, blin, out);
}

// round 8
// speedup vs baseline: 1.6070x; 1.0693x over previous
#include <cuda_runtime.h>

#define NNODES 50000
#define NGRAPH 64
#define FIN    128
#define NCLS   10
#define MAXE   600000
#define NBLK   ((NNODES + 255) / 256)   // 196 scan blocks

// ---------------- scratch (static device arrays) -----------------------------
__device__ float g_xlr1[NNODES * 256];   // conv1: [xl(128) | xr(128)]
__device__ float g_h1  [NNODES * 128];   // conv1 output (post-ELU)
__device__ float g_xlr2[NNODES * 128];   // conv2: [xl(64) | xr(64)]
__device__ float g_pool[NGRAPH * 64];
__device__ float g_cnt [NGRAPH];
__device__ int   g_idx64;

__device__ int   g_deg     [NNODES];
__device__ int   g_rowstart[NNODES + 1];
__device__ int   g_cursor  [NNODES];
__device__ int   g_csr_src [MAXE];
__device__ int   g_bsum    [NBLK];
__device__ int   g_boff    [NBLK];

// ---------------- helpers -----------------------------------------------------
__device__ __forceinline__ void red_add4(float* p, float4 v) {
    asm volatile("red.global.add.v4.f32 [%0], {%1,%2,%3,%4};"
                 :: "l"(p), "f"(v.x), "f"(v.y), "f"(v.z), "f"(v.w) : "memory");
}
__device__ __forceinline__ float lrelu(float v) { return v > 0.f ? v : 0.2f * v; }
__device__ __forceinline__ float elu(float v)   { return v > 0.f ? v : expm1f(v); }

// pack two floats into bf16x2 (first arg -> high half)
__device__ __forceinline__ unsigned packbf(float hi, float lo) {
    unsigned r;
    asm("cvt.rn.bf16x2.f32 %0, %1, %2;" : "=r"(r) : "f"(hi), "f"(lo));
    return r;
}
// split pair (v0 = low-k, v1 = high-k) into hi/lo bf16x2 words
__device__ __forceinline__ void bfsplit2(float v0, float v1,
                                         unsigned& h, unsigned& l) {
    h = packbf(v1, v0);
    float h0 = __uint_as_float(h << 16);
    float h1 = __uint_as_float(h & 0xffff0000u);
    l = packbf(v1 - h1, v0 - h0);
}
__device__ __forceinline__ void mma_bf16(float* c, const unsigned* a,
                                         const unsigned* b) {
    asm volatile(
        "mma.sync.aligned.m16n8k16.row.col.f32.bf16.bf16.f32 "
        "{%0,%1,%2,%3}, {%4,%5,%6,%7}, {%8,%9}, {%0,%1,%2,%3};"
        : "+f"(c[0]), "+f"(c[1]), "+f"(c[2]), "+f"(c[3])
        : "r"(a[0]), "r"(a[1]), "r"(a[2]), "r"(a[3]), "r"(b[0]), "r"(b[1]));
}

// ---------------- dtype detection --------------------------------------------
__global__ void detect_idx_kernel(const void* ei) {
    if (threadIdx.x == 0) {
        const long long* p = (const long long*)ei;
        int ok = 1;
        for (int i = 0; i < 16; i++) {
            long long v = p[i];
            if (v < 0 || v >= NNODES) ok = 0;
        }
        g_idx64 = ok;
    }
}

// ---------------- zero small accumulators ------------------------------------
__global__ void zero_kernel() {
    int i = blockIdx.x * blockDim.x + threadIdx.x;
    if (i < NNODES)      g_deg[i] = 0;
    if (i < NGRAPH * 64) g_pool[i] = 0.f;
    if (i < NGRAPH)      g_cnt[i]  = 0.f;
}

// ---------------- CSR build ---------------------------------------------------
__global__ void hist_kernel(const void* __restrict__ ei, int E) {
    int e = blockIdx.x * blockDim.x + threadIdx.x;
    if (e >= E) return;
    int d = g_idx64 ? (int)((const long long*)ei)[E + e]
                    : ((const int*)ei)[E + e];
    atomicAdd(&g_deg[d], 1);
}

__global__ void scan1_kernel() {
    int i = blockIdx.x * 256 + threadIdx.x;
    int v = (i < NNODES) ? g_deg[i] : 0;
    int s = v;
    #pragma unroll
    for (int off = 16; off; off >>= 1) s += __shfl_xor_sync(~0u, s, off);
    __shared__ int ws[8];
    if ((threadIdx.x & 31) == 0) ws[threadIdx.x >> 5] = s;
    __syncthreads();
    if (threadIdx.x == 0) {
        int t = 0;
        #pragma unroll
        for (int w = 0; w < 8; w++) t += ws[w];
        g_bsum[blockIdx.x] = t;
    }
}

__global__ void scan2_kernel() {
    __shared__ int sh[256];
    int t = threadIdx.x;
    int v = (t < NBLK) ? g_bsum[t] : 0;
    sh[t] = v;
    __syncthreads();
    for (int off = 1; off < 256; off <<= 1) {
        int u = (t >= off) ? sh[t - off] : 0;
        __syncthreads();
        sh[t] += u;
        __syncthreads();
    }
    if (t < NBLK) g_boff[t] = sh[t] - v;
}

__global__ void scan3_kernel() {
    int i = blockIdx.x * 256 + threadIdx.x;
    int lane = threadIdx.x & 31, warp = threadIdx.x >> 5;
    int v = (i < NNODES) ? g_deg[i] : 0;
    int x = v;
    #pragma unroll
    for (int off = 1; off < 32; off <<= 1) {
        int y = __shfl_up_sync(~0u, x, off);
        if (lane >= off) x += y;
    }
    __shared__ int ws[8];
    if (lane == 31) ws[warp] = x;
    __syncthreads();
    if (threadIdx.x == 0) {
        int run = 0;
        #pragma unroll
        for (int w = 0; w < 8; w++) { int tmp = ws[w]; ws[w] = run; run += tmp; }
    }
    __syncthreads();
    int incl = x + ws[warp];
    int base = g_boff[blockIdx.x];
    if (i < NNODES) {
        int rs = base + incl - v;
        g_rowstart[i] = rs;
        g_cursor[i]   = rs;
        if (i == NNODES - 1) g_rowstart[NNODES] = base + incl;
    }
}

__global__ void scatter_kernel(const void* __restrict__ ei, int E) {
    int e = blockIdx.x * blockDim.x + threadIdx.x;
    if (e >= E) return;
    int s, d;
    if (g_idx64) {
        const long long* p = (const long long*)ei;
        s = (int)p[e]; d = (int)p[E + e];
    } else {
        const int* p = (const int*)ei;
        s = p[e]; d = p[E + e];
    }
    int pos = atomicAdd(&g_cursor[d], 1);
    g_csr_src[pos] = s;
}

// ---------------- tensor-core dual-weight GEMM (bf16 3-term split) -----------
// BM=128, BN=64, 8 warps each 32x32. m16n8k16 bf16. Smem rows: 16 data uints
// (32 k as bf16x2 pairs) + 4 pad = pitch 20 -> conflict-free fragment loads.
#define AP 20
#define BP 20
__global__ __launch_bounds__(256) void gemm_tc(
        const float* __restrict__ A,
        const float* __restrict__ WL,
        const float* __restrict__ WR,
        float* __restrict__ C,
        int M, int NHALF, int NN) {
    __shared__ unsigned AsH[128 * AP], AsL[128 * AP];
    __shared__ unsigned BsH[64 * BP],  BsL[64 * BP];

    const int t = threadIdx.x;
    const int lane = t & 31, g = lane >> 2, tig = lane & 3;
    const int w = t >> 5, wr = w & 3, wc = w >> 2;   // warp tile 32x32
    const int rowBase = blockIdx.y << 7;
    const int colTile = blockIdx.x << 6;

    const float* W;
    int colBase;
    if (colTile >= NHALF) { W = WR; colBase = colTile - NHALF; }
    else                  { W = WL; colBase = colTile; }

    float acc[2][4][4];
    #pragma unroll
    for (int mi = 0; mi < 2; mi++)
        #pragma unroll
        for (int ni = 0; ni < 4; ni++)
            #pragma unroll
            for (int j = 0; j < 4; j++) acc[mi][ni][j] = 0.f;

    const int arow = t >> 3, aj = t & 7;          // A: float4 per thread
    const int bcol = t & 63, bk2 = (t >> 6) << 2; // B: 4 k-pairs per col

    for (int k0 = 0; k0 < FIN; k0 += 32) {
        #pragma unroll
        for (int r = 0; r < 4; r++) {
            int row = arow + r * 32;
            int grow = rowBase + row;
            if (grow >= M) grow = M - 1;
            float4 v = *(const float4*)&A[(long)grow * FIN + k0 + (aj << 2)];
            unsigned h0, l0, h1, l1;
            bfsplit2(v.x, v.y, h0, l0);
            bfsplit2(v.z, v.w, h1, l1);
            int ad = row * AP + aj * 2;
            AsH[ad] = h0; AsH[ad + 1] = h1;
            AsL[ad] = l0; AsL[ad + 1] = l1;
        }
        {
            unsigned h[4], l[4];
            #pragma unroll
            for (int j = 0; j < 4; j++) {
                int krow = k0 + 2 * (bk2 + j);
                float v0 = W[(long)krow * NHALF + colBase + bcol];
                float v1 = W[(long)(krow + 1) * NHALF + colBase + bcol];
                bfsplit2(v0, v1, h[j], l[j]);
            }
            *(uint4*)&BsH[bcol * BP + bk2] = make_uint4(h[0], h[1], h[2], h[3]);
            *(uint4*)&BsL[bcol * BP + bk2] = make_uint4(l[0], l[1], l[2], l[3]);
        }
        __syncthreads();

        #pragma unroll
        for (int kk2 = 0; kk2 < 16; kk2 += 8) {   // two K=16 steps
            unsigned ah[2][4], al[2][4], bh[4][2], bl[4][2];
            #pragma unroll
            for (int mi = 0; mi < 2; mi++) {
                int rb  = (wr * 32 + mi * 16 + g) * AP;
                int rb8 = rb + 8 * AP;
                ah[mi][0] = AsH[rb  + kk2 + tig];
                ah[mi][1] = AsH[rb8 + kk2 + tig];
                ah[mi][2] = AsH[rb  + kk2 + 4 + tig];
                ah[mi][3] = AsH[rb8 + kk2 + 4 + tig];
                al[mi][0] = AsL[rb  + kk2 + tig];
                al[mi][1] = AsL[rb8 + kk2 + tig];
                al[mi][2] = AsL[rb  + kk2 + 4 + tig];
                al[mi][3] = AsL[rb8 + kk2 + 4 + tig];
            }
            #pragma unroll
            for (int ni = 0; ni < 4; ni++) {
                int cb = (wc * 32 + ni * 8 + g) * BP;
                bh[ni][0] = BsH[cb + kk2 + tig];
                bh[ni][1] = BsH[cb + kk2 + 4 + tig];
                bl[ni][0] = BsL[cb + kk2 + tig];
                bl[ni][1] = BsL[cb + kk2 + 4 + tig];
            }
            #pragma unroll
            for (int mi = 0; mi < 2; mi++)
                #pragma unroll
                for (int ni = 0; ni < 4; ni++) {
                    mma_bf16(acc[mi][ni], ah[mi], bh[ni]);
                    mma_bf16(acc[mi][ni], ah[mi], bl[ni]);
                    mma_bf16(acc[mi][ni], al[mi], bh[ni]);
                }
        }
        __syncthreads();
    }

    #pragma unroll
    for (int mi = 0; mi < 2; mi++) {
        int row0 = rowBase + wr * 32 + mi * 16 + g;
        #pragma unroll
        for (int ni = 0; ni < 4; ni++) {
            int col = colTile + wc * 32 + ni * 8 + 2 * tig;
            if (row0 < M)
                *(float2*)&C[(long)row0 * NN + col] =
                    make_float2(acc[mi][ni][0], acc[mi][ni][1]);
            if (row0 + 8 < M)
                *(float2*)&C[(long)(row0 + 8) * NN + col] =
                    make_float2(acc[mi][ni][2], acc[mi][ni][3]);
        }
    }
}

// ---------------- conv1: warp/node, unroll-4 score chains --------------------
__global__ void conv1_kernel(const float* __restrict__ b1,
                             const float* __restrict__ att) {
    int w = (blockIdx.x * blockDim.x + threadIdx.x) >> 5;
    if (w >= NNODES) return;
    int lane = threadIdx.x & 31, c4 = lane << 2;

    float4 av = *(const float4*)&att[c4];
    float4 xr = *(const float4*)&g_xlr1[w * 256 + 128 + c4];
    float4 bb = *(const float4*)&b1[c4];

    float4 acc = make_float4(0.f, 0.f, 0.f, 0.f);
    float den = 0.f;

    int rs = g_rowstart[w], re = g_rowstart[w + 1];
    int cnt = re - rs + 1;                        // virtual edge 0 = self loop

    for (int i = 0; i < cnt; i += 4) {
        int s0 = (i == 0) ? w : g_csr_src[rs + i - 1];
        int s1 = (i + 1 < cnt) ? g_csr_src[rs + i]     : s0;
        int s2 = (i + 2 < cnt) ? g_csr_src[rs + i + 1] : s0;
        int s3 = (i + 3 < cnt) ? g_csr_src[rs + i + 2] : s0;
        float4 a0 = *(const float4*)&g_xlr1[(long)s0 * 256 + c4];
        float4 a1 = *(const float4*)&g_xlr1[(long)s1 * 256 + c4];
        float4 a2 = *(const float4*)&g_xlr1[(long)s2 * 256 + c4];
        float4 a3 = *(const float4*)&g_xlr1[(long)s3 * 256 + c4];

        float e0 = lrelu(a0.x + xr.x) * av.x + lrelu(a0.y + xr.y) * av.y +
                   lrelu(a0.z + xr.z) * av.z + lrelu(a0.w + xr.w) * av.w;
        float e1 = lrelu(a1.x + xr.x) * av.x + lrelu(a1.y + xr.y) * av.y +
                   lrelu(a1.z + xr.z) * av.z + lrelu(a1.w + xr.w) * av.w;
        float e2 = lrelu(a2.x + xr.x) * av.x + lrelu(a2.y + xr.y) * av.y +
                   lrelu(a2.z + xr.z) * av.z + lrelu(a2.w + xr.w) * av.w;
        float e3 = lrelu(a3.x + xr.x) * av.x + lrelu(a3.y + xr.y) * av.y +
                   lrelu(a3.z + xr.z) * av.z + lrelu(a3.w + xr.w) * av.w;
        #pragma unroll
        for (int off = 8; off; off >>= 1) {
            e0 += __shfl_xor_sync(0xffffffffu, e0, off);
            e1 += __shfl_xor_sync(0xffffffffu, e1, off);
            e2 += __shfl_xor_sync(0xffffffffu, e2, off);
            e3 += __shfl_xor_sync(0xffffffffu, e3, off);
        }
        float p0 = __expf(e0);
        float p1 = (i + 1 < cnt) ? __expf(e1) : 0.f;
        float p2 = (i + 2 < cnt) ? __expf(e2) : 0.f;
        float p3 = (i + 3 < cnt) ? __expf(e3) : 0.f;
        acc.x += p0 * a0.x + p1 * a1.x + p2 * a2.x + p3 * a3.x;
        acc.y += p0 * a0.y + p1 * a1.y + p2 * a2.y + p3 * a3.y;
        acc.z += p0 * a0.z + p1 * a1.z + p2 * a2.z + p3 * a3.z;
        acc.w += p0 * a0.w + p1 * a1.w + p2 * a2.w + p3 * a3.w;
        den += p0 + p1 + p2 + p3;
    }
    float inv = 1.f / den;
    float4 h;
    h.x = elu(acc.x * inv + bb.x);
    h.y = elu(acc.y * inv + bb.y);
    h.z = elu(acc.z * inv + bb.z);
    h.w = elu(acc.w * inv + bb.w);
    *(float4*)&g_h1[w * 128 + c4] = h;
}

// ---------------- conv2: 16 lanes/node, unroll-4, + mean-pool ----------------
__global__ void conv2_kernel(const float* __restrict__ b2,
                             const float* __restrict__ att,
                             const void* __restrict__ batch) {
    int idx = blockIdx.x * blockDim.x + threadIdx.x;
    int n = idx >> 4;
    if (n >= NNODES) return;
    int l = threadIdx.x & 15, c4 = l << 2;
    unsigned gmask = 0xFFFFu << (threadIdx.x & 16);

    float4 av = *(const float4*)&att[c4];
    float4 xr = *(const float4*)&g_xlr2[n * 128 + 64 + c4];
    float4 bb = *(const float4*)&b2[c4];

    float4 acc = make_float4(0.f, 0.f, 0.f, 0.f);
    float den = 0.f;

    int rs = g_rowstart[n], re = g_rowstart[n + 1];
    int cnt = re - rs + 1;

    for (int i = 0; i < cnt; i += 4) {
        int s0 = (i == 0) ? n : g_csr_src[rs + i - 1];
        int s1 = (i + 1 < cnt) ? g_csr_src[rs + i]     : s0;
        int s2 = (i + 2 < cnt) ? g_csr_src[rs + i + 1] : s0;
        int s3 = (i + 3 < cnt) ? g_csr_src[rs + i + 2] : s0;
        float4 a0 = *(const float4*)&g_xlr2[(long)s0 * 128 + c4];
        float4 a1 = *(const float4*)&g_xlr2[(long)s1 * 128 + c4];
        float4 a2 = *(const float4*)&g_xlr2[(long)s2 * 128 + c4];
        float4 a3 = *(const float4*)&g_xlr2[(long)s3 * 128 + c4];

        float e0 = lrelu(a0.x + xr.x) * av.x + lrelu(a0.y + xr.y) * av.y +
                   lrelu(a0.z + xr.z) * av.z + lrelu(a0.w + xr.w) * av.w;
        float e1 = lrelu(a1.x + xr.x) * av.x + lrelu(a1.y + xr.y) * av.y +
                   lrelu(a1.z + xr.z) * av.z + lrelu(a1.w + xr.w) * av.w;
        float e2 = lrelu(a2.x + xr.x) * av.x + lrelu(a2.y + xr.y) * av.y +
                   lrelu(a2.z + xr.z) * av.z + lrelu(a2.w + xr.w) * av.w;
        float e3 = lrelu(a3.x + xr.x) * av.x + lrelu(a3.y + xr.y) * av.y +
                   lrelu(a3.z + xr.z) * av.z + lrelu(a3.w + xr.w) * av.w;
        #pragma unroll
        for (int off = 8; off; off >>= 1) {
            e0 += __shfl_xor_sync(gmask, e0, off);
            e1 += __shfl_xor_sync(gmask, e1, off);
            e2 += __shfl_xor_sync(gmask, e2, off);
            e3 += __shfl_xor_sync(gmask, e3, off);
        }
        float p0 = __expf(e0);
        float p1 = (i + 1 < cnt) ? __expf(e1) : 0.f;
        float p2 = (i + 2 < cnt) ? __expf(e2) : 0.f;
        float p3 = (i + 3 < cnt) ? __expf(e3) : 0.f;
        acc.x += p0 * a0.x + p1 * a1.x + p2 * a2.x + p3 * a3.x;
        acc.y += p0 * a0.y + p1 * a1.y + p2 * a2.y + p3 * a3.y;
        acc.z += p0 * a0.z + p1 * a1.z + p2 * a2.z + p3 * a3.z;
        acc.w += p0 * a0.w + p1 * a1.w + p2 * a2.w + p3 * a3.w;
        den += p0 + p1 + p2 + p3;
    }
    float inv = 1.f / den;
    float4 h;
    h.x = elu(acc.x * inv + bb.x);
    h.y = elu(acc.y * inv + bb.y);
    h.z = elu(acc.z * inv + bb.z);
    h.w = elu(acc.w * inv + bb.w);

    int gph = g_idx64 ? (int)((const long long*)batch)[n]
                      : ((const int*)batch)[n];
    red_add4(&g_pool[gph * 64 + c4], h);
    if (l == 0) atomicAdd(&g_cnt[gph], 1.0f);
}

// ---------------- final: out = (pool/cnt) @ Wlin + blin ----------------------
__global__ void final_kernel(const float* __restrict__ Wlin,
                             const float* __restrict__ blin,
                             float* __restrict__ out) {
    int t = threadIdx.x;
    if (t >= NGRAPH * NCLS) return;
    int g = t / NCLS, j = t - g * NCLS;
    float inv = 1.f / fmaxf(g_cnt[g], 1.f);
    float s = 0.f;
    #pragma unroll
    for (int c = 0; c < 64; c++) s += g_pool[g * 64 + c] * Wlin[c * NCLS + j];
    out[t] = s * inv + blin[j];
}

// ---------------- launch ------------------------------------------------------
extern "C" void kernel_launch(void* const* d_in, const int* in_sizes, int n_in,
                              void* d_out, int out_size) {
    const float* x    = (const float*)d_in[0];
    const void*  ei   = d_in[1];
    const void*  bat  = d_in[2];
    const float* Wl1  = (const float*)d_in[3];
    const float* Wr1  = (const float*)d_in[4];
    const float* att1 = (const float*)d_in[5];
    const float* b1   = (const float*)d_in[6];
    const float* Wl2  = (const float*)d_in[7];
    const float* Wr2  = (const float*)d_in[8];
    const float* att2 = (const float*)d_in[9];
    const float* b2   = (const float*)d_in[10];
    const float* Wlin = (const float*)d_in[11];
    const float* blin = (const float*)d_in[12];
    float* out = (float*)d_out;

    int Nn = in_sizes[0] / 128;   // 50000
    int E  = in_sizes[1] / 2;     // 600000

    float *p_xlr1, *p_xlr2, *p_h1;
    cudaGetSymbolAddress((void**)&p_xlr1, g_xlr1);
    cudaGetSymbolAddress((void**)&p_xlr2, g_xlr2);
    cudaGetSymbolAddress((void**)&p_h1,   g_h1);

    detect_idx_kernel<<<1, 32>>>(ei);
    zero_kernel<<<(Nn + 255) / 256, 256>>>();
    hist_kernel<<<(E + 255) / 256, 256>>>(ei, E);

    dim3 g1(4, (Nn + 127) / 128);
    gemm_tc<<<g1, 256>>>(x, Wl1, Wr1, p_xlr1, Nn, 128, 256);   // profiled slot

    scan1_kernel<<<NBLK, 256>>>();
    scan2_kernel<<<1, 256>>>();
    scan3_kernel<<<NBLK, 256>>>();
    scatter_kernel<<<(E + 255) / 256, 256>>>(ei, E);

    conv1_kernel<<<(Nn * 32 + 255) / 256, 256>>>(b1, att1);

    dim3 g2(2, (Nn + 127) / 128);
    gemm_tc<<<g2, 256>>>(p_h1, Wl2, Wr2, p_xlr2, Nn, 64, 128);
    conv2_kernel<<<(Nn * 16 + 255) / 256, 256>>>(b2, att2, bat);

    final_kernel<<<1, 640>>>(Wlin, blin, out);
}

// round 9
// speedup vs baseline: 1.6594x; 1.0326x over previous
#include <cuda_runtime.h>

#define NNODES 50000
#define NGRAPH 64
#define FIN    128
#define NCLS   10
#define MAXE   600000
#define NBLK   ((NNODES + 255) / 256)   // 196 scan blocks

// ---------------- scratch (static device arrays) -----------------------------
__device__ float g_xlr1[NNODES * 256];   // conv1: [xl(128) | xr(128)]
__device__ float g_h1  [NNODES * 128];   // conv1 output (post-ELU)
__device__ float g_xlr2[NNODES * 128];   // conv2: [xl(64) | xr(64)]
__device__ float g_pool[NGRAPH * 64];
__device__ float g_cnt [NGRAPH];
__device__ int   g_idx64;

__device__ int   g_deg     [NNODES];
__device__ int   g_rowstart[NNODES + 1];
__device__ int   g_cursor  [NNODES];
__device__ int   g_csr_src [MAXE];
__device__ int   g_bsum    [NBLK];
__device__ int   g_boff    [NBLK];

// ---------------- helpers -----------------------------------------------------
__device__ __forceinline__ void red_add4(float* p, float4 v) {
    asm volatile("red.global.add.v4.f32 [%0], {%1,%2,%3,%4};"
                 :: "l"(p), "f"(v.x), "f"(v.y), "f"(v.z), "f"(v.w) : "memory");
}
__device__ __forceinline__ float lrelu(float v) { return v > 0.f ? v : 0.2f * v; }
__device__ __forceinline__ float elu(float v)   { return v > 0.f ? v : expm1f(v); }

// pack two floats into bf16x2 (first arg -> high half)
__device__ __forceinline__ unsigned packbf(float hi, float lo) {
    unsigned r;
    asm("cvt.rn.bf16x2.f32 %0, %1, %2;" : "=r"(r) : "f"(hi), "f"(lo));
    return r;
}
// split pair (v0 = low-k, v1 = high-k) into hi/lo bf16x2 words
__device__ __forceinline__ void bfsplit2(float v0, float v1,
                                         unsigned& h, unsigned& l) {
    h = packbf(v1, v0);
    float h0 = __uint_as_float(h << 16);
    float h1 = __uint_as_float(h & 0xffff0000u);
    l = packbf(v1 - h1, v0 - h0);
}
__device__ __forceinline__ void mma_bf16(float* c, const unsigned* a,
                                         const unsigned* b) {
    asm volatile(
        "mma.sync.aligned.m16n8k16.row.col.f32.bf16.bf16.f32 "
        "{%0,%1,%2,%3}, {%4,%5,%6,%7}, {%8,%9}, {%0,%1,%2,%3};"
        : "+f"(c[0]), "+f"(c[1]), "+f"(c[2]), "+f"(c[3])
        : "r"(a[0]), "r"(a[1]), "r"(a[2]), "r"(a[3]), "r"(b[0]), "r"(b[1]));
}

// ---------------- dtype detection --------------------------------------------
__global__ void detect_idx_kernel(const void* ei) {
    if (threadIdx.x == 0) {
        const long long* p = (const long long*)ei;
        int ok = 1;
        for (int i = 0; i < 16; i++) {
            long long v = p[i];
            if (v < 0 || v >= NNODES) ok = 0;
        }
        g_idx64 = ok;
    }
}

// ---------------- zero small accumulators ------------------------------------
__global__ void zero_kernel() {
    int i = blockIdx.x * blockDim.x + threadIdx.x;
    if (i < NNODES)      g_deg[i] = 0;
    if (i < NGRAPH * 64) g_pool[i] = 0.f;
    if (i < NGRAPH)      g_cnt[i]  = 0.f;
}

// ---------------- CSR build ---------------------------------------------------
__global__ void hist_kernel(const void* __restrict__ ei, int E) {
    int e = blockIdx.x * blockDim.x + threadIdx.x;
    if (e >= E) return;
    int d = g_idx64 ? (int)((const long long*)ei)[E + e]
                    : ((const int*)ei)[E + e];
    atomicAdd(&g_deg[d], 1);
}

__global__ void scan1_kernel() {
    int i = blockIdx.x * 256 + threadIdx.x;
    int v = (i < NNODES) ? g_deg[i] : 0;
    int s = v;
    #pragma unroll
    for (int off = 16; off; off >>= 1) s += __shfl_xor_sync(~0u, s, off);
    __shared__ int ws[8];
    if ((threadIdx.x & 31) == 0) ws[threadIdx.x >> 5] = s;
    __syncthreads();
    if (threadIdx.x == 0) {
        int t = 0;
        #pragma unroll
        for (int w = 0; w < 8; w++) t += ws[w];
        g_bsum[blockIdx.x] = t;
    }
}

__global__ void scan2_kernel() {
    __shared__ int sh[256];
    int t = threadIdx.x;
    int v = (t < NBLK) ? g_bsum[t] : 0;
    sh[t] = v;
    __syncthreads();
    for (int off = 1; off < 256; off <<= 1) {
        int u = (t >= off) ? sh[t - off] : 0;
        __syncthreads();
        sh[t] += u;
        __syncthreads();
    }
    if (t < NBLK) g_boff[t] = sh[t] - v;
}

__global__ void scan3_kernel() {
    int i = blockIdx.x * 256 + threadIdx.x;
    int lane = threadIdx.x & 31, warp = threadIdx.x >> 5;
    int v = (i < NNODES) ? g_deg[i] : 0;
    int x = v;
    #pragma unroll
    for (int off = 1; off < 32; off <<= 1) {
        int y = __shfl_up_sync(~0u, x, off);
        if (lane >= off) x += y;
    }
    __shared__ int ws[8];
    if (lane == 31) ws[warp] = x;
    __syncthreads();
    if (threadIdx.x == 0) {
        int run = 0;
        #pragma unroll
        for (int w = 0; w < 8; w++) { int tmp = ws[w]; ws[w] = run; run += tmp; }
    }
    __syncthreads();
    int incl = x + ws[warp];
    int base = g_boff[blockIdx.x];
    if (i < NNODES) {
        int rs = base + incl - v;
        g_rowstart[i] = rs;
        g_cursor[i]   = rs;
        if (i == NNODES - 1) g_rowstart[NNODES] = base + incl;
    }
}

__global__ void scatter_kernel(const void* __restrict__ ei, int E) {
    int e = blockIdx.x * blockDim.x + threadIdx.x;
    if (e >= E) return;
    int s, d;
    if (g_idx64) {
        const long long* p = (const long long*)ei;
        s = (int)p[e]; d = (int)p[E + e];
    } else {
        const int* p = (const int*)ei;
        s = p[e]; d = p[E + e];
    }
    int pos = atomicAdd(&g_cursor[d], 1);
    g_csr_src[pos] = s;
}

// ---------------- tensor-core dual-weight GEMM (bf16 3-term split) -----------
#define AP 20
#define BP 20
__global__ __launch_bounds__(256) void gemm_tc(
        const float* __restrict__ A,
        const float* __restrict__ WL,
        const float* __restrict__ WR,
        float* __restrict__ C,
        int M, int NHALF, int NN) {
    __shared__ unsigned AsH[128 * AP], AsL[128 * AP];
    __shared__ unsigned BsH[64 * BP],  BsL[64 * BP];

    const int t = threadIdx.x;
    const int lane = t & 31, g = lane >> 2, tig = lane & 3;
    const int w = t >> 5, wr = w & 3, wc = w >> 2;   // warp tile 32x32
    const int rowBase = blockIdx.y << 7;
    const int colTile = blockIdx.x << 6;

    const float* W;
    int colBase;
    if (colTile >= NHALF) { W = WR; colBase = colTile - NHALF; }
    else                  { W = WL; colBase = colTile; }

    float acc[2][4][4];
    #pragma unroll
    for (int mi = 0; mi < 2; mi++)
        #pragma unroll
        for (int ni = 0; ni < 4; ni++)
            #pragma unroll
            for (int j = 0; j < 4; j++) acc[mi][ni][j] = 0.f;

    const int arow = t >> 3, aj = t & 7;          // A: float4 per thread
    const int bcol = t & 63, bk2 = (t >> 6) << 2; // B: 4 k-pairs per col

    for (int k0 = 0; k0 < FIN; k0 += 32) {
        #pragma unroll
        for (int r = 0; r < 4; r++) {
            int row = arow + r * 32;
            int grow = rowBase + row;
            if (grow >= M) grow = M - 1;
            float4 v = *(const float4*)&A[(long)grow * FIN + k0 + (aj << 2)];
            unsigned h0, l0, h1, l1;
            bfsplit2(v.x, v.y, h0, l0);
            bfsplit2(v.z, v.w, h1, l1);
            int ad = row * AP + aj * 2;
            AsH[ad] = h0; AsH[ad + 1] = h1;
            AsL[ad] = l0; AsL[ad + 1] = l1;
        }
        {
            unsigned h[4], l[4];
            #pragma unroll
            for (int j = 0; j < 4; j++) {
                int krow = k0 + 2 * (bk2 + j);
                float v0 = W[(long)krow * NHALF + colBase + bcol];
                float v1 = W[(long)(krow + 1) * NHALF + colBase + bcol];
                bfsplit2(v0, v1, h[j], l[j]);
            }
            *(uint4*)&BsH[bcol * BP + bk2] = make_uint4(h[0], h[1], h[2], h[3]);
            *(uint4*)&BsL[bcol * BP + bk2] = make_uint4(l[0], l[1], l[2], l[3]);
        }
        __syncthreads();

        #pragma unroll
        for (int kk2 = 0; kk2 < 16; kk2 += 8) {   // two K=16 steps
            unsigned ah[2][4], al[2][4], bh[4][2], bl[4][2];
            #pragma unroll
            for (int mi = 0; mi < 2; mi++) {
                int rb  = (wr * 32 + mi * 16 + g) * AP;
                int rb8 = rb + 8 * AP;
                ah[mi][0] = AsH[rb  + kk2 + tig];
                ah[mi][1] = AsH[rb8 + kk2 + tig];
                ah[mi][2] = AsH[rb  + kk2 + 4 + tig];
                ah[mi][3] = AsH[rb8 + kk2 + 4 + tig];
                al[mi][0] = AsL[rb  + kk2 + tig];
                al[mi][1] = AsL[rb8 + kk2 + tig];
                al[mi][2] = AsL[rb  + kk2 + 4 + tig];
                al[mi][3] = AsL[rb8 + kk2 + 4 + tig];
            }
            #pragma unroll
            for (int ni = 0; ni < 4; ni++) {
                int cb = (wc * 32 + ni * 8 + g) * BP;
                bh[ni][0] = BsH[cb + kk2 + tig];
                bh[ni][1] = BsH[cb + kk2 + 4 + tig];
                bl[ni][0] = BsL[cb + kk2 + tig];
                bl[ni][1] = BsL[cb + kk2 + 4 + tig];
            }
            #pragma unroll
            for (int mi = 0; mi < 2; mi++)
                #pragma unroll
                for (int ni = 0; ni < 4; ni++) {
                    mma_bf16(acc[mi][ni], ah[mi], bh[ni]);
                    mma_bf16(acc[mi][ni], ah[mi], bl[ni]);
                    mma_bf16(acc[mi][ni], al[mi], bh[ni]);
                }
        }
        __syncthreads();
    }

    #pragma unroll
    for (int mi = 0; mi < 2; mi++) {
        int row0 = rowBase + wr * 32 + mi * 16 + g;
        #pragma unroll
        for (int ni = 0; ni < 4; ni++) {
            int col = colTile + wc * 32 + ni * 8 + 2 * tig;
            if (row0 < M)
                *(float2*)&C[(long)row0 * NN + col] =
                    make_float2(acc[mi][ni][0], acc[mi][ni][1]);
            if (row0 + 8 < M)
                *(float2*)&C[(long)(row0 + 8) * NN + col] =
                    make_float2(acc[mi][ni][2], acc[mi][ni][3]);
        }
    }
}

// ---------------- conv1: warp/node, unroll-4 score chains --------------------
__global__ void conv1_kernel(const float* __restrict__ b1,
                             const float* __restrict__ att) {
    int w = (blockIdx.x * blockDim.x + threadIdx.x) >> 5;
    if (w >= NNODES) return;
    int lane = threadIdx.x & 31, c4 = lane << 2;

    float4 av = *(const float4*)&att[c4];
    float4 xr = *(const float4*)&g_xlr1[w * 256 + 128 + c4];
    float4 bb = *(const float4*)&b1[c4];

    float4 acc = make_float4(0.f, 0.f, 0.f, 0.f);
    float den = 0.f;

    int rs = g_rowstart[w], re = g_rowstart[w + 1];
    int cnt = re - rs + 1;                        // virtual edge 0 = self loop

    for (int i = 0; i < cnt; i += 4) {
        int s0 = (i == 0) ? w : g_csr_src[rs + i - 1];
        int s1 = (i + 1 < cnt) ? g_csr_src[rs + i]     : s0;
        int s2 = (i + 2 < cnt) ? g_csr_src[rs + i + 1] : s0;
        int s3 = (i + 3 < cnt) ? g_csr_src[rs + i + 2] : s0;
        float4 a0 = *(const float4*)&g_xlr1[(long)s0 * 256 + c4];
        float4 a1 = *(const float4*)&g_xlr1[(long)s1 * 256 + c4];
        float4 a2 = *(const float4*)&g_xlr1[(long)s2 * 256 + c4];
        float4 a3 = *(const float4*)&g_xlr1[(long)s3 * 256 + c4];

        float e0 = lrelu(a0.x + xr.x) * av.x + lrelu(a0.y + xr.y) * av.y +
                   lrelu(a0.z + xr.z) * av.z + lrelu(a0.w + xr.w) * av.w;
        float e1 = lrelu(a1.x + xr.x) * av.x + lrelu(a1.y + xr.y) * av.y +
                   lrelu(a1.z + xr.z) * av.z + lrelu(a1.w + xr.w) * av.w;
        float e2 = lrelu(a2.x + xr.x) * av.x + lrelu(a2.y + xr.y) * av.y +
                   lrelu(a2.z + xr.z) * av.z + lrelu(a2.w + xr.w) * av.w;
        float e3 = lrelu(a3.x + xr.x) * av.x + lrelu(a3.y + xr.y) * av.y +
                   lrelu(a3.z + xr.z) * av.z + lrelu(a3.w + xr.w) * av.w;
        #pragma unroll
        for (int off = 8; off; off >>= 1) {
            e0 += __shfl_xor_sync(0xffffffffu, e0, off);
            e1 += __shfl_xor_sync(0xffffffffu, e1, off);
            e2 += __shfl_xor_sync(0xffffffffu, e2, off);
            e3 += __shfl_xor_sync(0xffffffffu, e3, off);
        }
        float p0 = __expf(e0);
        float p1 = (i + 1 < cnt) ? __expf(e1) : 0.f;
        float p2 = (i + 2 < cnt) ? __expf(e2) : 0.f;
        float p3 = (i + 3 < cnt) ? __expf(e3) : 0.f;
        acc.x += p0 * a0.x + p1 * a1.x + p2 * a2.x + p3 * a3.x;
        acc.y += p0 * a0.y + p1 * a1.y + p2 * a2.y + p3 * a3.y;
        acc.z += p0 * a0.z + p1 * a1.z + p2 * a2.z + p3 * a3.z;
        acc.w += p0 * a0.w + p1 * a1.w + p2 * a2.w + p3 * a3.w;
        den += p0 + p1 + p2 + p3;
    }
    float inv = 1.f / den;
    float4 h;
    h.x = elu(acc.x * inv + bb.x);
    h.y = elu(acc.y * inv + bb.y);
    h.z = elu(acc.z * inv + bb.z);
    h.w = elu(acc.w * inv + bb.w);
    *(float4*)&g_h1[w * 128 + c4] = h;
}

// ---------------- conv2: 16 lanes/node, unroll-4, + mean-pool ----------------
__global__ void conv2_kernel(const float* __restrict__ b2,
                             const float* __restrict__ att,
                             const void* __restrict__ batch) {
    int idx = blockIdx.x * blockDim.x + threadIdx.x;
    int n = idx >> 4;
    if (n >= NNODES) return;
    int l = threadIdx.x & 15, c4 = l << 2;
    unsigned gmask = 0xFFFFu << (threadIdx.x & 16);

    float4 av = *(const float4*)&att[c4];
    float4 xr = *(const float4*)&g_xlr2[n * 128 + 64 + c4];
    float4 bb = *(const float4*)&b2[c4];

    float4 acc = make_float4(0.f, 0.f, 0.f, 0.f);
    float den = 0.f;

    int rs = g_rowstart[n], re = g_rowstart[n + 1];
    int cnt = re - rs + 1;

    for (int i = 0; i < cnt; i += 4) {
        int s0 = (i == 0) ? n : g_csr_src[rs + i - 1];
        int s1 = (i + 1 < cnt) ? g_csr_src[rs + i]     : s0;
        int s2 = (i + 2 < cnt) ? g_csr_src[rs + i + 1] : s0;
        int s3 = (i + 3 < cnt) ? g_csr_src[rs + i + 2] : s0;
        float4 a0 = *(const float4*)&g_xlr2[(long)s0 * 128 + c4];
        float4 a1 = *(const float4*)&g_xlr2[(long)s1 * 128 + c4];
        float4 a2 = *(const float4*)&g_xlr2[(long)s2 * 128 + c4];
        float4 a3 = *(const float4*)&g_xlr2[(long)s3 * 128 + c4];

        float e0 = lrelu(a0.x + xr.x) * av.x + lrelu(a0.y + xr.y) * av.y +
                   lrelu(a0.z + xr.z) * av.z + lrelu(a0.w + xr.w) * av.w;
        float e1 = lrelu(a1.x + xr.x) * av.x + lrelu(a1.y + xr.y) * av.y +
                   lrelu(a1.z + xr.z) * av.z + lrelu(a1.w + xr.w) * av.w;
        float e2 = lrelu(a2.x + xr.x) * av.x + lrelu(a2.y + xr.y) * av.y +
                   lrelu(a2.z + xr.z) * av.z + lrelu(a2.w + xr.w) * av.w;
        float e3 = lrelu(a3.x + xr.x) * av.x + lrelu(a3.y + xr.y) * av.y +
                   lrelu(a3.z + xr.z) * av.z + lrelu(a3.w + xr.w) * av.w;
        #pragma unroll
        for (int off = 8; off; off >>= 1) {
            e0 += __shfl_xor_sync(gmask, e0, off);
            e1 += __shfl_xor_sync(gmask, e1, off);
            e2 += __shfl_xor_sync(gmask, e2, off);
            e3 += __shfl_xor_sync(gmask, e3, off);
        }
        float p0 = __expf(e0);
        float p1 = (i + 1 < cnt) ? __expf(e1) : 0.f;
        float p2 = (i + 2 < cnt) ? __expf(e2) : 0.f;
        float p3 = (i + 3 < cnt) ? __expf(e3) : 0.f;
        acc.x += p0 * a0.x + p1 * a1.x + p2 * a2.x + p3 * a3.x;
        acc.y += p0 * a0.y + p1 * a1.y + p2 * a2.y + p3 * a3.y;
        acc.z += p0 * a0.z + p1 * a1.z + p2 * a2.z + p3 * a3.z;
        acc.w += p0 * a0.w + p1 * a1.w + p2 * a2.w + p3 * a3.w;
        den += p0 + p1 + p2 + p3;
    }
    float inv = 1.f / den;
    float4 h;
    h.x = elu(acc.x * inv + bb.x);
    h.y = elu(acc.y * inv + bb.y);
    h.z = elu(acc.z * inv + bb.z);
    h.w = elu(acc.w * inv + bb.w);

    int gph = g_idx64 ? (int)((const long long*)batch)[n]
                      : ((const int*)batch)[n];
    red_add4(&g_pool[gph * 64 + c4], h);
    if (l == 0) atomicAdd(&g_cnt[gph], 1.0f);
}

// ---------------- final: out = (pool/cnt) @ Wlin + blin ----------------------
__global__ void final_kernel(const float* __restrict__ Wlin,
                             const float* __restrict__ blin,
                             float* __restrict__ out) {
    int t = threadIdx.x;
    if (t >= NGRAPH * NCLS) return;
    int g = t / NCLS, j = t - g * NCLS;
    float inv = 1.f / fmaxf(g_cnt[g], 1.f);
    float s = 0.f;
    #pragma unroll
    for (int c = 0; c < 64; c++) s += g_pool[g * 64 + c] * Wlin[c * NCLS + j];
    out[t] = s * inv + blin[j];
}

// ---------------- launch ------------------------------------------------------
extern "C" void kernel_launch(void* const* d_in, const int* in_sizes, int n_in,
                              void* d_out, int out_size) {
    const float* x    = (const float*)d_in[0];
    const void*  ei   = d_in[1];
    const void*  bat  = d_in[2];
    const float* Wl1  = (const float*)d_in[3];
    const float* Wr1  = (const float*)d_in[4];
    const float* att1 = (const float*)d_in[5];
    const float* b1   = (const float*)d_in[6];
    const float* Wl2  = (const float*)d_in[7];
    const float* Wr2  = (const float*)d_in[8];
    const float* att2 = (const float*)d_in[9];
    const float* b2   = (const float*)d_in[10];
    const float* Wlin = (const float*)d_in[11];
    const float* blin = (const float*)d_in[12];
    float* out = (float*)d_out;

    int Nn = in_sizes[0] / 128;   // 50000
    int E  = in_sizes[1] / 2;     // 600000

    float *p_xlr1, *p_xlr2, *p_h1;
    cudaGetSymbolAddress((void**)&p_xlr1, g_xlr1);
    cudaGetSymbolAddress((void**)&p_xlr2, g_xlr2);
    cudaGetSymbolAddress((void**)&p_h1,   g_h1);

    // side stream + events, created once (host-side objects; no device mem)
    static cudaStream_t s1 = nullptr;
    static cudaEvent_t evFork = nullptr, evJoin = nullptr;
    if (s1 == nullptr) {
        cudaStreamCreateWithFlags(&s1, cudaStreamNonBlocking);
        cudaEventCreateWithFlags(&evFork, cudaEventDisableTiming);
        cudaEventCreateWithFlags(&evJoin, cudaEventDisableTiming);
    }

    // ---- fork: gemm1 on s1, CSR build on main stream, concurrently ----
    cudaEventRecord(evFork, 0);
    cudaStreamWaitEvent(s1, evFork, 0);

    dim3 g1(4, (Nn + 127) / 128);
    gemm_tc<<<g1, 256, 0, s1>>>(x, Wl1, Wr1, p_xlr1, Nn, 128, 256);
    cudaEventRecord(evJoin, s1);

    detect_idx_kernel<<<1, 32>>>(ei);
    zero_kernel<<<(Nn + 255) / 256, 256>>>();
    hist_kernel<<<(E + 255) / 256, 256>>>(ei, E);
    scan1_kernel<<<NBLK, 256>>>();
    scan2_kernel<<<1, 256>>>();
    scan3_kernel<<<NBLK, 256>>>();
    scatter_kernel<<<(E + 255) / 256, 256>>>(ei, E);

    // ---- join: conv1 needs both gemm1 and the CSR ----
    cudaStreamWaitEvent(0, evJoin, 0);

    conv1_kernel<<<(Nn * 32 + 255) / 256, 256>>>(b1, att1);

    dim3 g2(2, (Nn + 127) / 128);
    gemm_tc<<<g2, 256>>>(p_h1, Wl2, Wr2, p_xlr2, Nn, 64, 128);
    conv2_kernel<<<(Nn * 16 + 255) / 256, 256>>>(b2, att2, bat);

    final_kernel<<<1, 640>>>(Wlin, blin, out);
}

// round 10
// speedup vs baseline: 1.6645x; 1.0030x over previous
#include <cuda_runtime.h>
#include <cuda_fp16.h>

#define NNODES 50000
#define NGRAPH 64
#define FIN    128
#define NCLS   10
#define MAXE   600000
#define NBLK   ((NNODES + 255) / 256)   // 196 scan blocks

// ---------------- scratch (static device arrays) -----------------------------
__device__ __half g_xlr1h[NNODES * 256]; // conv1 operand: [xl(128)|xr(128)] fp16
__device__ float  g_h1  [NNODES * 128];  // conv1 output (post-ELU), fp32
__device__ __half g_xlr2h[NNODES * 128]; // conv2 operand: [xl(64)|xr(64)] fp16
__device__ float  g_pool[NGRAPH * 64];
__device__ float  g_cnt [NGRAPH];
__device__ int    g_idx64;

__device__ int   g_deg     [NNODES];
__device__ int   g_rowstart[NNODES + 1];
__device__ int   g_cursor  [NNODES];
__device__ int   g_csr_src [MAXE];
__device__ int   g_bsum    [NBLK];
__device__ int   g_boff    [NBLK];

// ---------------- helpers -----------------------------------------------------
__device__ __forceinline__ void red_add4(float* p, float4 v) {
    asm volatile("red.global.add.v4.f32 [%0], {%1,%2,%3,%4};"
                 :: "l"(p), "f"(v.x), "f"(v.y), "f"(v.z), "f"(v.w) : "memory");
}
__device__ __forceinline__ float lrelu(float v) { return v > 0.f ? v : 0.2f * v; }
__device__ __forceinline__ float elu(float v)   { return v > 0.f ? v : expm1f(v); }

// fp16 gather: 4 consecutive channels starting at half-index base (8B aligned)
__device__ __forceinline__ float4 ldh4(const __half* p) {
    uint2 r = *(const uint2*)p;
    float2 u = __half22float2(*(const __half2*)&r.x);
    float2 v = __half22float2(*(const __half2*)&r.y);
    return make_float4(u.x, u.y, v.x, v.y);
}

// pack two floats into bf16x2 (first arg -> high half)
__device__ __forceinline__ unsigned packbf(float hi, float lo) {
    unsigned r;
    asm("cvt.rn.bf16x2.f32 %0, %1, %2;" : "=r"(r) : "f"(hi), "f"(lo));
    return r;
}
// split pair (v0 = low-k, v1 = high-k) into hi/lo bf16x2 words
__device__ __forceinline__ void bfsplit2(float v0, float v1,
                                         unsigned& h, unsigned& l) {
    h = packbf(v1, v0);
    float h0 = __uint_as_float(h << 16);
    float h1 = __uint_as_float(h & 0xffff0000u);
    l = packbf(v1 - h1, v0 - h0);
}
__device__ __forceinline__ void mma_bf16(float* c, const unsigned* a,
                                         const unsigned* b) {
    asm volatile(
        "mma.sync.aligned.m16n8k16.row.col.f32.bf16.bf16.f32 "
        "{%0,%1,%2,%3}, {%4,%5,%6,%7}, {%8,%9}, {%0,%1,%2,%3};"
        : "+f"(c[0]), "+f"(c[1]), "+f"(c[2]), "+f"(c[3])
        : "r"(a[0]), "r"(a[1]), "r"(a[2]), "r"(a[3]), "r"(b[0]), "r"(b[1]));
}

// ---------------- dtype detection + zero (fused) ------------------------------
__global__ void init_kernel(const void* ei) {
    int i = blockIdx.x * blockDim.x + threadIdx.x;
    if (i == 0) {
        const long long* p = (const long long*)ei;
        int ok = 1;
        for (int k = 0; k < 16; k++) {
            long long v = p[k];
            if (v < 0 || v >= NNODES) ok = 0;
        }
        g_idx64 = ok;
    }
    if (i < NNODES)      g_deg[i] = 0;
    if (i < NGRAPH * 64) g_pool[i] = 0.f;
    if (i < NGRAPH)      g_cnt[i]  = 0.f;
}

// ---------------- CSR build ---------------------------------------------------
__global__ void hist_kernel(const void* __restrict__ ei, int E) {
    int e = blockIdx.x * blockDim.x + threadIdx.x;
    if (e >= E) return;
    int d = g_idx64 ? (int)((const long long*)ei)[E + e]
                    : ((const int*)ei)[E + e];
    atomicAdd(&g_deg[d], 1);
}

__global__ void scan1_kernel() {
    int i = blockIdx.x * 256 + threadIdx.x;
    int v = (i < NNODES) ? g_deg[i] : 0;
    int s = v;
    #pragma unroll
    for (int off = 16; off; off >>= 1) s += __shfl_xor_sync(~0u, s, off);
    __shared__ int ws[8];
    if ((threadIdx.x & 31) == 0) ws[threadIdx.x >> 5] = s;
    __syncthreads();
    if (threadIdx.x == 0) {
        int t = 0;
        #pragma unroll
        for (int w = 0; w < 8; w++) t += ws[w];
        g_bsum[blockIdx.x] = t;
    }
}

__global__ void scan2_kernel() {
    __shared__ int sh[256];
    int t = threadIdx.x;
    int v = (t < NBLK) ? g_bsum[t] : 0;
    sh[t] = v;
    __syncthreads();
    for (int off = 1; off < 256; off <<= 1) {
        int u = (t >= off) ? sh[t - off] : 0;
        __syncthreads();
        sh[t] += u;
        __syncthreads();
    }
    if (t < NBLK) g_boff[t] = sh[t] - v;
}

__global__ void scan3_kernel() {
    int i = blockIdx.x * 256 + threadIdx.x;
    int lane = threadIdx.x & 31, warp = threadIdx.x >> 5;
    int v = (i < NNODES) ? g_deg[i] : 0;
    int x = v;
    #pragma unroll
    for (int off = 1; off < 32; off <<= 1) {
        int y = __shfl_up_sync(~0u, x, off);
        if (lane >= off) x += y;
    }
    __shared__ int ws[8];
    if (lane == 31) ws[warp] = x;
    __syncthreads();
    if (threadIdx.x == 0) {
        int run = 0;
        #pragma unroll
        for (int w = 0; w < 8; w++) { int tmp = ws[w]; ws[w] = run; run += tmp; }
    }
    __syncthreads();
    int incl = x + ws[warp];
    int base = g_boff[blockIdx.x];
    if (i < NNODES) {
        int rs = base + incl - v;
        g_rowstart[i] = rs;
        g_cursor[i]   = rs;
        if (i == NNODES - 1) g_rowstart[NNODES] = base + incl;
    }
}

__global__ void scatter_kernel(const void* __restrict__ ei, int E) {
    int e = blockIdx.x * blockDim.x + threadIdx.x;
    if (e >= E) return;
    int s, d;
    if (g_idx64) {
        const long long* p = (const long long*)ei;
        s = (int)p[e]; d = (int)p[E + e];
    } else {
        const int* p = (const int*)ei;
        s = p[e]; d = p[E + e];
    }
    int pos = atomicAdd(&g_cursor[d], 1);
    g_csr_src[pos] = s;
}

// ---------------- tensor-core dual-weight GEMM (bf16 split, fp16 out) --------
#define AP 20
#define BP 20
__global__ __launch_bounds__(256) void gemm_tc(
        const float* __restrict__ A,
        const float* __restrict__ WL,
        const float* __restrict__ WR,
        __half* __restrict__ C,
        int M, int NHALF, int NN) {
    __shared__ unsigned AsH[128 * AP], AsL[128 * AP];
    __shared__ unsigned BsH[64 * BP],  BsL[64 * BP];

    const int t = threadIdx.x;
    const int lane = t & 31, g = lane >> 2, tig = lane & 3;
    const int w = t >> 5, wr = w & 3, wc = w >> 2;   // warp tile 32x32
    const int rowBase = blockIdx.y << 7;
    const int colTile = blockIdx.x << 6;

    const float* W;
    int colBase;
    if (colTile >= NHALF) { W = WR; colBase = colTile - NHALF; }
    else                  { W = WL; colBase = colTile; }

    float acc[2][4][4];
    #pragma unroll
    for (int mi = 0; mi < 2; mi++)
        #pragma unroll
        for (int ni = 0; ni < 4; ni++)
            #pragma unroll
            for (int j = 0; j < 4; j++) acc[mi][ni][j] = 0.f;

    const int arow = t >> 3, aj = t & 7;          // A: float4 per thread
    const int bcol = t & 63, bk2 = (t >> 6) << 2; // B: 4 k-pairs per col

    for (int k0 = 0; k0 < FIN; k0 += 32) {
        #pragma unroll
        for (int r = 0; r < 4; r++) {
            int row = arow + r * 32;
            int grow = rowBase + row;
            if (grow >= M) grow = M - 1;
            float4 v = *(const float4*)&A[(long)grow * FIN + k0 + (aj << 2)];
            unsigned h0, l0, h1, l1;
            bfsplit2(v.x, v.y, h0, l0);
            bfsplit2(v.z, v.w, h1, l1);
            int ad = row * AP + aj * 2;
            AsH[ad] = h0; AsH[ad + 1] = h1;
            AsL[ad] = l0; AsL[ad + 1] = l1;
        }
        {
            unsigned h[4], l[4];
            #pragma unroll
            for (int j = 0; j < 4; j++) {
                int krow = k0 + 2 * (bk2 + j);
                float v0 = W[(long)krow * NHALF + colBase + bcol];
                float v1 = W[(long)(krow + 1) * NHALF + colBase + bcol];
                bfsplit2(v0, v1, h[j], l[j]);
            }
            *(uint4*)&BsH[bcol * BP + bk2] = make_uint4(h[0], h[1], h[2], h[3]);
            *(uint4*)&BsL[bcol * BP + bk2] = make_uint4(l[0], l[1], l[2], l[3]);
        }
        __syncthreads();

        #pragma unroll
        for (int kk2 = 0; kk2 < 16; kk2 += 8) {   // two K=16 steps
            unsigned ah[2][4], al[2][4], bh[4][2], bl[4][2];
            #pragma unroll
            for (int mi = 0; mi < 2; mi++) {
                int rb  = (wr * 32 + mi * 16 + g) * AP;
                int rb8 = rb + 8 * AP;
                ah[mi][0] = AsH[rb  + kk2 + tig];
                ah[mi][1] = AsH[rb8 + kk2 + tig];
                ah[mi][2] = AsH[rb  + kk2 + 4 + tig];
                ah[mi][3] = AsH[rb8 + kk2 + 4 + tig];
                al[mi][0] = AsL[rb  + kk2 + tig];
                al[mi][1] = AsL[rb8 + kk2 + tig];
                al[mi][2] = AsL[rb  + kk2 + 4 + tig];
                al[mi][3] = AsL[rb8 + kk2 + 4 + tig];
            }
            #pragma unroll
            for (int ni = 0; ni < 4; ni++) {
                int cb = (wc * 32 + ni * 8 + g) * BP;
                bh[ni][0] = BsH[cb + kk2 + tig];
                bh[ni][1] = BsH[cb + kk2 + 4 + tig];
                bl[ni][0] = BsL[cb + kk2 + tig];
                bl[ni][1] = BsL[cb + kk2 + 4 + tig];
            }
            #pragma unroll
            for (int mi = 0; mi < 2; mi++)
                #pragma unroll
                for (int ni = 0; ni < 4; ni++) {
                    mma_bf16(acc[mi][ni], ah[mi], bh[ni]);
                    mma_bf16(acc[mi][ni], ah[mi], bl[ni]);
                    mma_bf16(acc[mi][ni], al[mi], bh[ni]);
                }
        }
        __syncthreads();
    }

    #pragma unroll
    for (int mi = 0; mi < 2; mi++) {
        int row0 = rowBase + wr * 32 + mi * 16 + g;
        #pragma unroll
        for (int ni = 0; ni < 4; ni++) {
            int col = colTile + wc * 32 + ni * 8 + 2 * tig;
            if (row0 < M)
                *(__half2*)&C[(long)row0 * NN + col] =
                    __floats2half2_rn(acc[mi][ni][0], acc[mi][ni][1]);
            if (row0 + 8 < M)
                *(__half2*)&C[(long)(row0 + 8) * NN + col] =
                    __floats2half2_rn(acc[mi][ni][2], acc[mi][ni][3]);
        }
    }
}

// ---------------- conv1: warp/node, fp16 gathers, unroll-4 -------------------
__global__ void conv1_kernel(const float* __restrict__ b1,
                             const float* __restrict__ att) {
    int w = (blockIdx.x * blockDim.x + threadIdx.x) >> 5;
    if (w >= NNODES) return;
    int lane = threadIdx.x & 31, c4 = lane << 2;

    float4 av = *(const float4*)&att[c4];
    float4 xr = ldh4(&g_xlr1h[(long)w * 256 + 128 + c4]);
    float4 bb = *(const float4*)&b1[c4];

    float4 acc = make_float4(0.f, 0.f, 0.f, 0.f);
    float den = 0.f;

    int rs = g_rowstart[w], re = g_rowstart[w + 1];
    int cnt = re - rs + 1;                        // virtual edge 0 = self loop

    for (int i = 0; i < cnt; i += 4) {
        int s0 = (i == 0) ? w : g_csr_src[rs + i - 1];
        int s1 = (i + 1 < cnt) ? g_csr_src[rs + i]     : s0;
        int s2 = (i + 2 < cnt) ? g_csr_src[rs + i + 1] : s0;
        int s3 = (i + 3 < cnt) ? g_csr_src[rs + i + 2] : s0;
        float4 a0 = ldh4(&g_xlr1h[(long)s0 * 256 + c4]);
        float4 a1 = ldh4(&g_xlr1h[(long)s1 * 256 + c4]);
        float4 a2 = ldh4(&g_xlr1h[(long)s2 * 256 + c4]);
        float4 a3 = ldh4(&g_xlr1h[(long)s3 * 256 + c4]);

        float e0 = lrelu(a0.x + xr.x) * av.x + lrelu(a0.y + xr.y) * av.y +
                   lrelu(a0.z + xr.z) * av.z + lrelu(a0.w + xr.w) * av.w;
        float e1 = lrelu(a1.x + xr.x) * av.x + lrelu(a1.y + xr.y) * av.y +
                   lrelu(a1.z + xr.z) * av.z + lrelu(a1.w + xr.w) * av.w;
        float e2 = lrelu(a2.x + xr.x) * av.x + lrelu(a2.y + xr.y) * av.y +
                   lrelu(a2.z + xr.z) * av.z + lrelu(a2.w + xr.w) * av.w;
        float e3 = lrelu(a3.x + xr.x) * av.x + lrelu(a3.y + xr.y) * av.y +
                   lrelu(a3.z + xr.z) * av.z + lrelu(a3.w + xr.w) * av.w;
        #pragma unroll
        for (int off = 8; off; off >>= 1) {
            e0 += __shfl_xor_sync(0xffffffffu, e0, off);
            e1 += __shfl_xor_sync(0xffffffffu, e1, off);
            e2 += __shfl_xor_sync(0xffffffffu, e2, off);
            e3 += __shfl_xor_sync(0xffffffffu, e3, off);
        }
        float p0 = __expf(e0);
        float p1 = (i + 1 < cnt) ? __expf(e1) : 0.f;
        float p2 = (i + 2 < cnt) ? __expf(e2) : 0.f;
        float p3 = (i + 3 < cnt) ? __expf(e3) : 0.f;
        acc.x += p0 * a0.x + p1 * a1.x + p2 * a2.x + p3 * a3.x;
        acc.y += p0 * a0.y + p1 * a1.y + p2 * a2.y + p3 * a3.y;
        acc.z += p0 * a0.z + p1 * a1.z + p2 * a2.z + p3 * a3.z;
        acc.w += p0 * a0.w + p1 * a1.w + p2 * a2.w + p3 * a3.w;
        den += p0 + p1 + p2 + p3;
    }
    float inv = 1.f / den;
    float4 h;
    h.x = elu(acc.x * inv + bb.x);
    h.y = elu(acc.y * inv + bb.y);
    h.z = elu(acc.z * inv + bb.z);
    h.w = elu(acc.w * inv + bb.w);
    *(float4*)&g_h1[w * 128 + c4] = h;
}

// ---------------- conv2: 16 lanes/node, fp16 gathers, unroll-4 ---------------
__global__ void conv2_kernel(const float* __restrict__ b2,
                             const float* __restrict__ att,
                             const void* __restrict__ batch) {
    int idx = blockIdx.x * blockDim.x + threadIdx.x;
    int n = idx >> 4;
    if (n >= NNODES) return;
    int l = threadIdx.x & 15, c4 = l << 2;
    unsigned gmask = 0xFFFFu << (threadIdx.x & 16);

    float4 av = *(const float4*)&att[c4];
    float4 xr = ldh4(&g_xlr2h[(long)n * 128 + 64 + c4]);
    float4 bb = *(const float4*)&b2[c4];

    float4 acc = make_float4(0.f, 0.f, 0.f, 0.f);
    float den = 0.f;

    int rs = g_rowstart[n], re = g_rowstart[n + 1];
    int cnt = re - rs + 1;

    for (int i = 0; i < cnt; i += 4) {
        int s0 = (i == 0) ? n : g_csr_src[rs + i - 1];
        int s1 = (i + 1 < cnt) ? g_csr_src[rs + i]     : s0;
        int s2 = (i + 2 < cnt) ? g_csr_src[rs + i + 1] : s0;
        int s3 = (i + 3 < cnt) ? g_csr_src[rs + i + 2] : s0;
        float4 a0 = ldh4(&g_xlr2h[(long)s0 * 128 + c4]);
        float4 a1 = ldh4(&g_xlr2h[(long)s1 * 128 + c4]);
        float4 a2 = ldh4(&g_xlr2h[(long)s2 * 128 + c4]);
        float4 a3 = ldh4(&g_xlr2h[(long)s3 * 128 + c4]);

        float e0 = lrelu(a0.x + xr.x) * av.x + lrelu(a0.y + xr.y) * av.y +
                   lrelu(a0.z + xr.z) * av.z + lrelu(a0.w + xr.w) * av.w;
        float e1 = lrelu(a1.x + xr.x) * av.x + lrelu(a1.y + xr.y) * av.y +
                   lrelu(a1.z + xr.z) * av.z + lrelu(a1.w + xr.w) * av.w;
        float e2 = lrelu(a2.x + xr.x) * av.x + lrelu(a2.y + xr.y) * av.y +
                   lrelu(a2.z + xr.z) * av.z + lrelu(a2.w + xr.w) * av.w;
        float e3 = lrelu(a3.x + xr.x) * av.x + lrelu(a3.y + xr.y) * av.y +
                   lrelu(a3.z + xr.z) * av.z + lrelu(a3.w + xr.w) * av.w;
        #pragma unroll
        for (int off = 8; off; off >>= 1) {
            e0 += __shfl_xor_sync(gmask, e0, off);
            e1 += __shfl_xor_sync(gmask, e1, off);
            e2 += __shfl_xor_sync(gmask, e2, off);
            e3 += __shfl_xor_sync(gmask, e3, off);
        }
        float p0 = __expf(e0);
        float p1 = (i + 1 < cnt) ? __expf(e1) : 0.f;
        float p2 = (i + 2 < cnt) ? __expf(e2) : 0.f;
        float p3 = (i + 3 < cnt) ? __expf(e3) : 0.f;
        acc.x += p0 * a0.x + p1 * a1.x + p2 * a2.x + p3 * a3.x;
        acc.y += p0 * a0.y + p1 * a1.y + p2 * a2.y + p3 * a3.y;
        acc.z += p0 * a0.z + p1 * a1.z + p2 * a2.z + p3 * a3.z;
        acc.w += p0 * a0.w + p1 * a1.w + p2 * a2.w + p3 * a3.w;
        den += p0 + p1 + p2 + p3;
    }
    float inv = 1.f / den;
    float4 h;
    h.x = elu(acc.x * inv + bb.x);
    h.y = elu(acc.y * inv + bb.y);
    h.z = elu(acc.z * inv + bb.z);
    h.w = elu(acc.w * inv + bb.w);

    int gph = g_idx64 ? (int)((const long long*)batch)[n]
                      : ((const int*)batch)[n];
    red_add4(&g_pool[gph * 64 + c4], h);
    if (l == 0) atomicAdd(&g_cnt[gph], 1.0f);
}

// ---------------- final: out = (pool/cnt) @ Wlin + blin ----------------------
__global__ void final_kernel(const float* __restrict__ Wlin,
                             const float* __restrict__ blin,
                             float* __restrict__ out) {
    int t = threadIdx.x;
    if (t >= NGRAPH * NCLS) return;
    int g = t / NCLS, j = t - g * NCLS;
    float inv = 1.f / fmaxf(g_cnt[g], 1.f);
    float s = 0.f;
    #pragma unroll
    for (int c = 0; c < 64; c++) s += g_pool[g * 64 + c] * Wlin[c * NCLS + j];
    out[t] = s * inv + blin[j];
}

// ---------------- launch ------------------------------------------------------
extern "C" void kernel_launch(void* const* d_in, const int* in_sizes, int n_in,
                              void* d_out, int out_size) {
    const float* x    = (const float*)d_in[0];
    const void*  ei   = d_in[1];
    const void*  bat  = d_in[2];
    const float* Wl1  = (const float*)d_in[3];
    const float* Wr1  = (const float*)d_in[4];
    const float* att1 = (const float*)d_in[5];
    const float* b1   = (const float*)d_in[6];
    const float* Wl2  = (const float*)d_in[7];
    const float* Wr2  = (const float*)d_in[8];
    const float* att2 = (const float*)d_in[9];
    const float* b2   = (const float*)d_in[10];
    const float* Wlin = (const float*)d_in[11];
    const float* blin = (const float*)d_in[12];
    float* out = (float*)d_out;

    int Nn = in_sizes[0] / 128;   // 50000
    int E  = in_sizes[1] / 2;     // 600000

    __half *p_xlr1, *p_xlr2;
    float *p_h1;
    cudaGetSymbolAddress((void**)&p_xlr1, g_xlr1h);
    cudaGetSymbolAddress((void**)&p_xlr2, g_xlr2h);
    cudaGetSymbolAddress((void**)&p_h1,   g_h1);

    // side stream + events, created once (host-side objects; no device mem)
    static cudaStream_t s1 = nullptr;
    static cudaEvent_t evFork = nullptr, evJoin = nullptr;
    if (s1 == nullptr) {
        cudaStreamCreateWithFlags(&s1, cudaStreamNonBlocking);
        cudaEventCreateWithFlags(&evFork, cudaEventDisableTiming);
        cudaEventCreateWithFlags(&evJoin, cudaEventDisableTiming);
    }

    // ---- fork: gemm1 on s1, CSR build on main stream, concurrently ----
    cudaEventRecord(evFork, 0);
    cudaStreamWaitEvent(s1, evFork, 0);

    dim3 g1(4, (Nn + 127) / 128);
    gemm_tc<<<g1, 256, 0, s1>>>(x, Wl1, Wr1, p_xlr1, Nn, 128, 256);
    cudaEventRecord(evJoin, s1);

    init_kernel<<<(Nn + 255) / 256, 256>>>(ei);
    hist_kernel<<<(E + 255) / 256, 256>>>(ei, E);
    scan1_kernel<<<NBLK, 256>>>();
    scan2_kernel<<<1, 256>>>();
    scan3_kernel<<<NBLK, 256>>>();
    scatter_kernel<<<(E + 255) / 256, 256>>>(ei, E);

    // ---- join: conv1 needs both gemm1 and the CSR ----
    cudaStreamWaitEvent(0, evJoin, 0);

    conv1_kernel<<<(Nn * 32 + 255) / 256, 256>>>(b1, att1);

    dim3 g2(2, (Nn + 127) / 128);
    gemm_tc<<<g2, 256>>>(p_h1, Wl2, Wr2, p_xlr2, Nn, 64, 128);
    conv2_kernel<<<(Nn * 16 + 255) / 256, 256>>>(b2, att2, bat);

    final_kernel<<<1, 640>>>(Wlin, blin, out);
}

// round 11
// speedup vs baseline: 1.7228x; 1.0351x over previous
#include <cuda_runtime.h>
#include <cuda_fp16.h>

#define NNODES 50000
#define NGRAPH 64
#define FIN    128
#define NCLS   10
#define MAXE   600000
#define NBLK   ((NNODES + 255) / 256)   // 196 scan blocks

// ---------------- scratch (static device arrays) -----------------------------
__device__ __half g_xlr1h[NNODES * 256]; // conv1 operand: [xl(128)|xr(128)] fp16
__device__ float  g_h1  [NNODES * 128];  // conv1 output (post-ELU), fp32
__device__ __half g_xlr2h[NNODES * 128]; // conv2 operand: [xl(64)|xr(64)] fp16
__device__ float  g_pool[NGRAPH * 64];
__device__ float  g_cnt [NGRAPH];
__device__ int    g_idx64;

__device__ int   g_deg     [NNODES];
__device__ int   g_rowstart[NNODES + 1];
__device__ int   g_cursor  [NNODES];
__device__ int   g_csr_src [MAXE];
__device__ int   g_bsum    [NBLK];
__device__ int   g_boff    [NBLK];

// ---------------- helpers -----------------------------------------------------
__device__ __forceinline__ void red_add4(float* p, float4 v) {
    asm volatile("red.global.add.v4.f32 [%0], {%1,%2,%3,%4};"
                 :: "l"(p), "f"(v.x), "f"(v.y), "f"(v.z), "f"(v.w) : "memory");
}
__device__ __forceinline__ float lrelu(float v) { return v > 0.f ? v : 0.2f * v; }
__device__ __forceinline__ float elu(float v)   { return v > 0.f ? v : expm1f(v); }

// load 8 consecutive fp16 channels (16B) and widen to 8 floats
__device__ __forceinline__ void ldh8(const __half* p, float* f) {
    uint4 r = *(const uint4*)p;
    float2 a = __half22float2(*(const __half2*)&r.x);
    float2 b = __half22float2(*(const __half2*)&r.y);
    float2 c = __half22float2(*(const __half2*)&r.z);
    float2 d = __half22float2(*(const __half2*)&r.w);
    f[0] = a.x; f[1] = a.y; f[2] = b.x; f[3] = b.y;
    f[4] = c.x; f[5] = c.y; f[6] = d.x; f[7] = d.y;
}

// pack two floats into bf16x2 (first arg -> high half)
__device__ __forceinline__ unsigned packbf(float hi, float lo) {
    unsigned r;
    asm("cvt.rn.bf16x2.f32 %0, %1, %2;" : "=r"(r) : "f"(hi), "f"(lo));
    return r;
}
__device__ __forceinline__ void bfsplit2(float v0, float v1,
                                         unsigned& h, unsigned& l) {
    h = packbf(v1, v0);
    float h0 = __uint_as_float(h << 16);
    float h1 = __uint_as_float(h & 0xffff0000u);
    l = packbf(v1 - h1, v0 - h0);
}
__device__ __forceinline__ void mma_bf16(float* c, const unsigned* a,
                                         const unsigned* b) {
    asm volatile(
        "mma.sync.aligned.m16n8k16.row.col.f32.bf16.bf16.f32 "
        "{%0,%1,%2,%3}, {%4,%5,%6,%7}, {%8,%9}, {%0,%1,%2,%3};"
        : "+f"(c[0]), "+f"(c[1]), "+f"(c[2]), "+f"(c[3])
        : "r"(a[0]), "r"(a[1]), "r"(a[2]), "r"(a[3]), "r"(b[0]), "r"(b[1]));
}

// ---------------- dtype detection + zero (fused) ------------------------------
__global__ void init_kernel(const void* ei) {
    int i = blockIdx.x * blockDim.x + threadIdx.x;
    if (i == 0) {
        const long long* p = (const long long*)ei;
        int ok = 1;
        for (int k = 0; k < 16; k++) {
            long long v = p[k];
            if (v < 0 || v >= NNODES) ok = 0;
        }
        g_idx64 = ok;
    }
    if (i < NNODES)      g_deg[i] = 0;
    if (i < NGRAPH * 64) g_pool[i] = 0.f;
    if (i < NGRAPH)      g_cnt[i]  = 0.f;
}

// ---------------- CSR build ---------------------------------------------------
__global__ void hist_kernel(const void* __restrict__ ei, int E) {
    int e = blockIdx.x * blockDim.x + threadIdx.x;
    if (e >= E) return;
    int d = g_idx64 ? (int)((const long long*)ei)[E + e]
                    : ((const int*)ei)[E + e];
    atomicAdd(&g_deg[d], 1);
}

__global__ void scan1_kernel() {
    int i = blockIdx.x * 256 + threadIdx.x;
    int v = (i < NNODES) ? g_deg[i] : 0;
    int s = v;
    #pragma unroll
    for (int off = 16; off; off >>= 1) s += __shfl_xor_sync(~0u, s, off);
    __shared__ int ws[8];
    if ((threadIdx.x & 31) == 0) ws[threadIdx.x >> 5] = s;
    __syncthreads();
    if (threadIdx.x == 0) {
        int t = 0;
        #pragma unroll
        for (int w = 0; w < 8; w++) t += ws[w];
        g_bsum[blockIdx.x] = t;
    }
}

__global__ void scan2_kernel() {
    __shared__ int sh[256];
    int t = threadIdx.x;
    int v = (t < NBLK) ? g_bsum[t] : 0;
    sh[t] = v;
    __syncthreads();
    for (int off = 1; off < 256; off <<= 1) {
        int u = (t >= off) ? sh[t - off] : 0;
        __syncthreads();
        sh[t] += u;
        __syncthreads();
    }
    if (t < NBLK) g_boff[t] = sh[t] - v;
}

__global__ void scan3_kernel() {
    int i = blockIdx.x * 256 + threadIdx.x;
    int lane = threadIdx.x & 31, warp = threadIdx.x >> 5;
    int v = (i < NNODES) ? g_deg[i] : 0;
    int x = v;
    #pragma unroll
    for (int off = 1; off < 32; off <<= 1) {
        int y = __shfl_up_sync(~0u, x, off);
        if (lane >= off) x += y;
    }
    __shared__ int ws[8];
    if (lane == 31) ws[warp] = x;
    __syncthreads();
    if (threadIdx.x == 0) {
        int run = 0;
        #pragma unroll
        for (int w = 0; w < 8; w++) { int tmp = ws[w]; ws[w] = run; run += tmp; }
    }
    __syncthreads();
    int incl = x + ws[warp];
    int base = g_boff[blockIdx.x];
    if (i < NNODES) {
        int rs = base + incl - v;
        g_rowstart[i] = rs;
        g_cursor[i]   = rs;
        if (i == NNODES - 1) g_rowstart[NNODES] = base + incl;
    }
}

__global__ void scatter_kernel(const void* __restrict__ ei, int E) {
    int e = blockIdx.x * blockDim.x + threadIdx.x;
    if (e >= E) return;
    int s, d;
    if (g_idx64) {
        const long long* p = (const long long*)ei;
        s = (int)p[e]; d = (int)p[E + e];
    } else {
        const int* p = (const int*)ei;
        s = p[e]; d = p[E + e];
    }
    int pos = atomicAdd(&g_cursor[d], 1);
    g_csr_src[pos] = s;
}

// ---------------- tensor-core dual-weight GEMM (bf16 split, fp16 out) --------
#define AP 20
#define BP 20
__global__ __launch_bounds__(256) void gemm_tc(
        const float* __restrict__ A,
        const float* __restrict__ WL,
        const float* __restrict__ WR,
        __half* __restrict__ C,
        int M, int NHALF, int NN) {
    __shared__ unsigned AsH[128 * AP], AsL[128 * AP];
    __shared__ unsigned BsH[64 * BP],  BsL[64 * BP];

    const int t = threadIdx.x;
    const int lane = t & 31, g = lane >> 2, tig = lane & 3;
    const int w = t >> 5, wr = w & 3, wc = w >> 2;   // warp tile 32x32
    const int rowBase = blockIdx.y << 7;
    const int colTile = blockIdx.x << 6;

    const float* W;
    int colBase;
    if (colTile >= NHALF) { W = WR; colBase = colTile - NHALF; }
    else                  { W = WL; colBase = colTile; }

    float acc[2][4][4];
    #pragma unroll
    for (int mi = 0; mi < 2; mi++)
        #pragma unroll
        for (int ni = 0; ni < 4; ni++)
            #pragma unroll
            for (int j = 0; j < 4; j++) acc[mi][ni][j] = 0.f;

    const int arow = t >> 3, aj = t & 7;          // A: float4 per thread
    const int bcol = t & 63, bk2 = (t >> 6) << 2; // B: 4 k-pairs per col

    for (int k0 = 0; k0 < FIN; k0 += 32) {
        #pragma unroll
        for (int r = 0; r < 4; r++) {
            int row = arow + r * 32;
            int grow = rowBase + row;
            if (grow >= M) grow = M - 1;
            float4 v = *(const float4*)&A[(long)grow * FIN + k0 + (aj << 2)];
            unsigned h0, l0, h1, l1;
            bfsplit2(v.x, v.y, h0, l0);
            bfsplit2(v.z, v.w, h1, l1);
            int ad = row * AP + aj * 2;
            AsH[ad] = h0; AsH[ad + 1] = h1;
            AsL[ad] = l0; AsL[ad + 1] = l1;
        }
        {
            unsigned h[4], l[4];
            #pragma unroll
            for (int j = 0; j < 4; j++) {
                int krow = k0 + 2 * (bk2 + j);
                float v0 = W[(long)krow * NHALF + colBase + bcol];
                float v1 = W[(long)(krow + 1) * NHALF + colBase + bcol];
                bfsplit2(v0, v1, h[j], l[j]);
            }
            *(uint4*)&BsH[bcol * BP + bk2] = make_uint4(h[0], h[1], h[2], h[3]);
            *(uint4*)&BsL[bcol * BP + bk2] = make_uint4(l[0], l[1], l[2], l[3]);
        }
        __syncthreads();

        #pragma unroll
        for (int kk2 = 0; kk2 < 16; kk2 += 8) {   // two K=16 steps
            unsigned ah[2][4], al[2][4], bh[4][2], bl[4][2];
            #pragma unroll
            for (int mi = 0; mi < 2; mi++) {
                int rb  = (wr * 32 + mi * 16 + g) * AP;
                int rb8 = rb + 8 * AP;
                ah[mi][0] = AsH[rb  + kk2 + tig];
                ah[mi][1] = AsH[rb8 + kk2 + tig];
                ah[mi][2] = AsH[rb  + kk2 + 4 + tig];
                ah[mi][3] = AsH[rb8 + kk2 + 4 + tig];
                al[mi][0] = AsL[rb  + kk2 + tig];
                al[mi][1] = AsL[rb8 + kk2 + tig];
                al[mi][2] = AsL[rb  + kk2 + 4 + tig];
                al[mi][3] = AsL[rb8 + kk2 + 4 + tig];
            }
            #pragma unroll
            for (int ni = 0; ni < 4; ni++) {
                int cb = (wc * 32 + ni * 8 + g) * BP;
                bh[ni][0] = BsH[cb + kk2 + tig];
                bh[ni][1] = BsH[cb + kk2 + 4 + tig];
                bl[ni][0] = BsL[cb + kk2 + tig];
                bl[ni][1] = BsL[cb + kk2 + 4 + tig];
            }
            #pragma unroll
            for (int mi = 0; mi < 2; mi++)
                #pragma unroll
                for (int ni = 0; ni < 4; ni++) {
                    mma_bf16(acc[mi][ni], ah[mi], bh[ni]);
                    mma_bf16(acc[mi][ni], ah[mi], bl[ni]);
                    mma_bf16(acc[mi][ni], al[mi], bh[ni]);
                }
        }
        __syncthreads();
    }

    #pragma unroll
    for (int mi = 0; mi < 2; mi++) {
        int row0 = rowBase + wr * 32 + mi * 16 + g;
        #pragma unroll
        for (int ni = 0; ni < 4; ni++) {
            int col = colTile + wc * 32 + ni * 8 + 2 * tig;
            if (row0 < M)
                *(__half2*)&C[(long)row0 * NN + col] =
                    __floats2half2_rn(acc[mi][ni][0], acc[mi][ni][1]);
            if (row0 + 8 < M)
                *(__half2*)&C[(long)(row0 + 8) * NN + col] =
                    __floats2half2_rn(acc[mi][ni][2], acc[mi][ni][3]);
        }
    }
}

// ---------------- conv1: 16 lanes/node (8 ch/lane), 2 nodes/warp, unroll-2 ---
__global__ void conv1_kernel(const float* __restrict__ b1,
                             const float* __restrict__ att) {
    int n = (blockIdx.x * blockDim.x + threadIdx.x) >> 4;   // node (2 per warp)
    int l = threadIdx.x & 15;                               // lane in node group
    int c8 = l << 3;                                        // channel base

    float av[8], xr[8], bb[8], acc[8];
    *(float4*)&av[0] = *(const float4*)&att[c8];
    *(float4*)&av[4] = *(const float4*)&att[c8 + 4];
    *(float4*)&bb[0] = *(const float4*)&b1[c8];
    *(float4*)&bb[4] = *(const float4*)&b1[c8 + 4];
    ldh8(&g_xlr1h[(long)n * 256 + 128 + c8], xr);
    #pragma unroll
    for (int j = 0; j < 8; j++) acc[j] = 0.f;
    float den = 0.f;

    int rs = g_rowstart[n], re = g_rowstart[n + 1];
    int cnt = re - rs + 1;                        // edge 0 = self loop
    int mcnt = max(cnt, __shfl_xor_sync(~0u, cnt, 16));

    for (int i = 0; i < mcnt; i += 2) {
        bool v0 = i < cnt, v1 = i + 1 < cnt;
        int s0 = (i == 0) ? n : (v0 ? g_csr_src[rs + i - 1] : n);
        int s1 = v1 ? g_csr_src[rs + i] : n;
        float a0[8], a1[8];
        ldh8(&g_xlr1h[(long)s0 * 256 + c8], a0);
        ldh8(&g_xlr1h[(long)s1 * 256 + c8], a1);

        float e0 = 0.f, e1 = 0.f;
        #pragma unroll
        for (int j = 0; j < 8; j++) {
            e0 += lrelu(a0[j] + xr[j]) * av[j];
            e1 += lrelu(a1[j] + xr[j]) * av[j];
        }
        #pragma unroll
        for (int off = 4; off; off >>= 1) {       // head group = 8 lanes
            e0 += __shfl_xor_sync(~0u, e0, off);
            e1 += __shfl_xor_sync(~0u, e1, off);
        }
        float p0 = v0 ? __expf(e0) : 0.f;
        float p1 = v1 ? __expf(e1) : 0.f;
        #pragma unroll
        for (int j = 0; j < 8; j++) acc[j] += p0 * a0[j] + p1 * a1[j];
        den += p0 + p1;
    }
    float inv = 1.f / den;
    float h[8];
    #pragma unroll
    for (int j = 0; j < 8; j++) h[j] = elu(acc[j] * inv + bb[j]);
    *(float4*)&g_h1[(long)n * 128 + c8]     = *(float4*)&h[0];
    *(float4*)&g_h1[(long)n * 128 + c8 + 4] = *(float4*)&h[4];
}

// ---------------- conv2: 8 lanes/node (8 ch/lane), 4 nodes/warp, unroll-2 ----
__global__ void conv2_kernel(const float* __restrict__ b2,
                             const float* __restrict__ att,
                             const void* __restrict__ batch) {
    int n = (blockIdx.x * blockDim.x + threadIdx.x) >> 3;
    if (n >= NNODES) return;
    int l = threadIdx.x & 7;
    int c8 = l << 3;

    float av[8], xr[8], bb[8], acc[8];
    *(float4*)&av[0] = *(const float4*)&att[c8];
    *(float4*)&av[4] = *(const float4*)&att[c8 + 4];
    *(float4*)&bb[0] = *(const float4*)&b2[c8];
    *(float4*)&bb[4] = *(const float4*)&b2[c8 + 4];
    ldh8(&g_xlr2h[(long)n * 128 + 64 + c8], xr);
    #pragma unroll
    for (int j = 0; j < 8; j++) acc[j] = 0.f;
    float den = 0.f;

    int rs = g_rowstart[n], re = g_rowstart[n + 1];
    int cnt = re - rs + 1;
    int mcnt = max(cnt, __shfl_xor_sync(~0u, cnt, 8));
    mcnt = max(mcnt, __shfl_xor_sync(~0u, mcnt, 16));

    for (int i = 0; i < mcnt; i += 2) {
        bool v0 = i < cnt, v1 = i + 1 < cnt;
        int s0 = (i == 0) ? n : (v0 ? g_csr_src[rs + i - 1] : n);
        int s1 = v1 ? g_csr_src[rs + i] : n;
        float a0[8], a1[8];
        ldh8(&g_xlr2h[(long)s0 * 128 + c8], a0);
        ldh8(&g_xlr2h[(long)s1 * 128 + c8], a1);

        float e0 = 0.f, e1 = 0.f;
        #pragma unroll
        for (int j = 0; j < 8; j++) {
            e0 += lrelu(a0[j] + xr[j]) * av[j];
            e1 += lrelu(a1[j] + xr[j]) * av[j];
        }
        #pragma unroll
        for (int off = 4; off; off >>= 1) {       // node group = 8 lanes
            e0 += __shfl_xor_sync(~0u, e0, off);
            e1 += __shfl_xor_sync(~0u, e1, off);
        }
        float p0 = v0 ? __expf(e0) : 0.f;
        float p1 = v1 ? __expf(e1) : 0.f;
        #pragma unroll
        for (int j = 0; j < 8; j++) acc[j] += p0 * a0[j] + p1 * a1[j];
        den += p0 + p1;
    }
    float inv = 1.f / den;
    float h[8];
    #pragma unroll
    for (int j = 0; j < 8; j++) h[j] = elu(acc[j] * inv + bb[j]);

    int gph = g_idx64 ? (int)((const long long*)batch)[n]
                      : ((const int*)batch)[n];
    red_add4(&g_pool[gph * 64 + c8],     *(float4*)&h[0]);
    red_add4(&g_pool[gph * 64 + c8 + 4], *(float4*)&h[4]);
    if (l == 0) atomicAdd(&g_cnt[gph], 1.0f);
}

// ---------------- final: out = (pool/cnt) @ Wlin + blin ----------------------
__global__ void final_kernel(const float* __restrict__ Wlin,
                             const float* __restrict__ blin,
                             float* __restrict__ out) {
    int t = threadIdx.x;
    if (t >= NGRAPH * NCLS) return;
    int g = t / NCLS, j = t - g * NCLS;
    float inv = 1.f / fmaxf(g_cnt[g], 1.f);
    float s = 0.f;
    #pragma unroll
    for (int c = 0; c < 64; c++) s += g_pool[g * 64 + c] * Wlin[c * NCLS + j];
    out[t] = s * inv + blin[j];
}

// ---------------- launch ------------------------------------------------------
extern "C" void kernel_launch(void* const* d_in, const int* in_sizes, int n_in,
                              void* d_out, int out_size) {
    const float* x    = (const float*)d_in[0];
    const void*  ei   = d_in[1];
    const void*  bat  = d_in[2];
    const float* Wl1  = (const float*)d_in[3];
    const float* Wr1  = (const float*)d_in[4];
    const float* att1 = (const float*)d_in[5];
    const float* b1   = (const float*)d_in[6];
    const float* Wl2  = (const float*)d_in[7];
    const float* Wr2  = (const float*)d_in[8];
    const float* att2 = (const float*)d_in[9];
    const float* b2   = (const float*)d_in[10];
    const float* Wlin = (const float*)d_in[11];
    const float* blin = (const float*)d_in[12];
    float* out = (float*)d_out;

    int Nn = in_sizes[0] / 128;   // 50000
    int E  = in_sizes[1] / 2;     // 600000

    __half *p_xlr1, *p_xlr2;
    float *p_h1;
    cudaGetSymbolAddress((void**)&p_xlr1, g_xlr1h);
    cudaGetSymbolAddress((void**)&p_xlr2, g_xlr2h);
    cudaGetSymbolAddress((void**)&p_h1,   g_h1);

    // side stream + events, created once (host-side objects; no device mem)
    static cudaStream_t s1 = nullptr;
    static cudaEvent_t evFork = nullptr, evJoin = nullptr;
    if (s1 == nullptr) {
        cudaStreamCreateWithFlags(&s1, cudaStreamNonBlocking);
        cudaEventCreateWithFlags(&evFork, cudaEventDisableTiming);
        cudaEventCreateWithFlags(&evJoin, cudaEventDisableTiming);
    }

    // ---- fork: gemm1 on s1, CSR build on main stream, concurrently ----
    cudaEventRecord(evFork, 0);
    cudaStreamWaitEvent(s1, evFork, 0);

    dim3 g1(4, (Nn + 127) / 128);
    gemm_tc<<<g1, 256, 0, s1>>>(x, Wl1, Wr1, p_xlr1, Nn, 128, 256);
    cudaEventRecord(evJoin, s1);

    init_kernel<<<(Nn + 255) / 256, 256>>>(ei);
    hist_kernel<<<(E + 255) / 256, 256>>>(ei, E);
    scan1_kernel<<<NBLK, 256>>>();
    scan2_kernel<<<1, 256>>>();
    scan3_kernel<<<NBLK, 256>>>();
    scatter_kernel<<<(E + 255) / 256, 256>>>(ei, E);

    // ---- join: conv1 needs both gemm1 and the CSR ----
    cudaStreamWaitEvent(0, evJoin, 0);

    conv1_kernel<<<(Nn * 16 + 255) / 256, 256>>>(b1, att1);

    dim3 g2(2, (Nn + 127) / 128);
    gemm_tc<<<g2, 256>>>(p_h1, Wl2, Wr2, p_xlr2, Nn, 64, 128);
    conv2_kernel<<<(Nn * 8 + 255) / 256, 256>>>(b2, att2, bat);

    final_kernel<<<1, 640>>>(Wlin, blin, out);
}